// round 7
// baseline (speedup 1.0000x reference)
#include <cuda_runtime.h>

#define NQ 6
#define NL 3

typedef unsigned long long ull;

// Weight-only part of each gate: M = RZ(w2) @ RY(w1) @ RZ(w0), complex 2x2.
__device__ float2 g_M[NL * NQ * 4];

__global__ void setup_gates(const float* __restrict__ w) {
    int g = threadIdx.x;
    if (g >= NL * NQ) return;
    float w0 = w[g * 3 + 0];
    float w1 = w[g * 3 + 1];
    float w2 = w[g * 3 + 2];
    float s1, c1, sp_, cp_, sm2, cm2;
    sincosf(0.5f * w1, &s1, &c1);
    sincosf(0.5f * (w0 + w2), &sp_, &cp_);
    sincosf(0.5f * (w0 - w2), &sm2, &cm2);
    g_M[g * 4 + 0] = make_float2(c1 * cp_, -c1 * sp_);   // M00
    g_M[g * 4 + 1] = make_float2(-s1 * cm2, -s1 * sm2);  // M01
    g_M[g * 4 + 2] = make_float2(s1 * cm2, -s1 * sm2);   // M10
    g_M[g * 4 + 3] = make_float2(c1 * cp_, c1 * sp_);    // M11
}

// ---- packed f32x2 helpers ----
__device__ __forceinline__ ull fma2(ull a, ull b, ull c) {
    ull d; asm("fma.rn.f32x2 %0,%1,%2,%3;" : "=l"(d) : "l"(a), "l"(b), "l"(c)); return d;
}
__device__ __forceinline__ ull mul2(ull a, ull b) {
    ull d; asm("mul.rn.f32x2 %0,%1,%2;" : "=l"(d) : "l"(a), "l"(b)); return d;
}
__device__ __forceinline__ ull add2(ull a, ull b) {
    ull d; asm("add.rn.f32x2 %0,%1,%2;" : "=l"(d) : "l"(a), "l"(b)); return d;
}
__device__ __forceinline__ ull pk(float lo, float hi) {
    ull d; asm("mov.b64 %0,{%1,%2};" : "=l"(d) : "f"(lo), "f"(hi)); return d;
}
__device__ __forceinline__ ull sp2(float x) { return pk(x, x); }
__device__ __forceinline__ float flo(ull v) { return __uint_as_float((unsigned)v); }
__device__ __forceinline__ float fhi(ull v) { return __uint_as_float((unsigned)(v >> 32)); }
__device__ __forceinline__ ull lsw(ull v) { return pk(fhi(v), flo(v)); }     // lane swap
__device__ __forceinline__ ull neg2(ull v) { return v ^ 0x8000000080000000ULL; }  // ALU
__device__ __forceinline__ float tanh_fast(float x) {
    float y; asm("tanh.approx.f32 %0, %1;" : "=f"(y) : "f"(x)); return y;
}

// Packed gate-coefficient construction: G = M @ RY(c,s), each Pij = (Gij.x, Gij.y).
// 8 packed fma-pipe ops (vs 16 scalar FFMA).
__device__ __forceinline__ void makeGp(const ull* m, float c, float s,
                                       ull& P00, ull& P01, ull& P10, ull& P11) {
    ull c2 = sp2(c), s2 = sp2(s), ns2 = neg2(s2);
    P00 = fma2(c2, m[0], mul2(s2, m[1]));
    P01 = fma2(c2, m[1], mul2(ns2, m[0]));
    P10 = fma2(c2, m[2], mul2(s2, m[3]));
    P11 = fma2(c2, m[3], mul2(ns2, m[2]));
}

// Gate on local wire w in {1..4}: pack-index stride S = 1<<(4-w). Element-wise packed.
// Splats/negations of the coefficient pairs are ALU ops (fill FFMA2 dead slots).
template <int S>
__device__ __forceinline__ void gate_local(ull* RE, ull* IM,
                                           ull P00, ull P01, ull P10, ull P11) {
    ull x00 = sp2(flo(P00)), y00 = sp2(fhi(P00)), ny00 = neg2(y00);
    ull x01 = sp2(flo(P01)), y01 = sp2(fhi(P01)), ny01 = neg2(y01);
    ull x10 = sp2(flo(P10)), y10 = sp2(fhi(P10)), ny10 = neg2(y10);
    ull x11 = sp2(flo(P11)), y11 = sp2(fhi(P11)), ny11 = neg2(y11);
#pragma unroll
    for (int t = 0; t < 8; t++) {
        int K0 = ((t & ~(S - 1)) << 1) | (t & (S - 1));
        int K1 = K0 + S;
        ull r0 = RE[K0], i0 = IM[K0], r1 = RE[K1], i1 = IM[K1];
        RE[K0] = fma2(x00, r0, fma2(ny00, i0, fma2(x01, r1, mul2(ny01, i1))));
        IM[K0] = fma2(x00, i0, fma2(y00, r0, fma2(x01, i1, mul2(y01, r1))));
        RE[K1] = fma2(x10, r0, fma2(ny10, i0, fma2(x11, r1, mul2(ny11, i1))));
        IM[K1] = fma2(x10, i0, fma2(y10, r0, fma2(x11, i1, mul2(y11, r1))));
    }
}

// Gate on wire 5 (the two lanes inside each pack), swap-form:
// out = P .* st + Q .* laneswap(st), P=(G00,G11), Q=(G01,G10).
__device__ __forceinline__ void gate_w5(ull* RE, ull* IM,
                                        ull P00, ull P01, ull P10, ull P11) {
    ull Px = pk(flo(P00), flo(P11)), Py = pk(fhi(P00), fhi(P11)), nPy = neg2(Py);
    ull Qx = pk(flo(P01), flo(P10)), Qy = pk(fhi(P01), fhi(P10)), nQy = neg2(Qy);
#pragma unroll
    for (int K = 0; K < 16; K++) {
        ull r = RE[K], i = IM[K];
        ull rs = lsw(r), is = lsw(i);
        RE[K] = fma2(Px, r, fma2(nPy, i, fma2(Qx, rs, mul2(nQy, is))));
        IM[K] = fma2(Px, i, fma2(Py, r, fma2(Qx, is, mul2(Qy, rs))));
    }
}

// Gate on wire 0 fused with a PENDING cnot(5,0) from the preceding ring.
// Gd/Go are (x,y) coefficient pairs; asymmetric packs absorb the lane merge:
//   out = pk(Gd,Go) .* mine + pk(Go,Gd) .* partner
__device__ __forceinline__ void gate_w0_fused(ull* RE, ull* IM, ull Gd, ull Go) {
    ull dx = pk(flo(Gd), flo(Go)), ox = pk(flo(Go), flo(Gd));
    ull dy = pk(fhi(Gd), fhi(Go)), oy = pk(fhi(Go), fhi(Gd));
    ull ndy = neg2(dy), noy = neg2(oy);
#pragma unroll
    for (int K = 0; K < 16; K++) {
        ull pr = __shfl_xor_sync(0xffffffffu, RE[K], 1);
        ull pi = __shfl_xor_sync(0xffffffffu, IM[K], 1);
        ull r = RE[K], i = IM[K];
        RE[K] = fma2(dx, r, fma2(ndy, i, fma2(ox, pr, mul2(noy, pi))));
        IM[K] = fma2(dx, i, fma2(dy, r, fma2(ox, pi, mul2(oy, pr))));
    }
}

__device__ __forceinline__ void swp(ull& a, ull& b) { ull t = a; a = b; b = t; }

// CNOT ring WITHOUT the final cnot(5,0): (0,1)(1,2)(2,3)(3,4)(4,5).
// The trailing cnot(5,0) is fused into the next wire-0 gate (or readout).
__device__ __forceinline__ void cnot_ring_partial(ull* RE, ull* IM, int p) {
    // cnot(0,1): p==1 threads flip pack bit3
    {
        bool pb = (p != 0);
#pragma unroll
        for (int K = 0; K < 8; K++) {
            ull a = RE[K], b = RE[K + 8];
            RE[K] = pb ? b : a; RE[K + 8] = pb ? a : b;
            ull c = IM[K], d = IM[K + 8];
            IM[K] = pb ? d : c; IM[K + 8] = pb ? c : d;
        }
    }
    // cnot(1,2): bit3==1 -> flip bit2  (free renames)
    swp(RE[8], RE[12]); swp(IM[8], IM[12]);
    swp(RE[9], RE[13]); swp(IM[9], IM[13]);
    swp(RE[10], RE[14]); swp(IM[10], IM[14]);
    swp(RE[11], RE[15]); swp(IM[11], IM[15]);
    // cnot(2,3): bit2==1 -> flip bit1
    swp(RE[4], RE[6]);  swp(IM[4], IM[6]);
    swp(RE[5], RE[7]);  swp(IM[5], IM[7]);
    swp(RE[12], RE[14]); swp(IM[12], IM[14]);
    swp(RE[13], RE[15]); swp(IM[13], IM[15]);
    // cnot(3,4): bit1==1 -> flip bit0
    swp(RE[2], RE[3]);  swp(IM[2], IM[3]);
    swp(RE[6], RE[7]);  swp(IM[6], IM[7]);
    swp(RE[10], RE[11]); swp(IM[10], IM[11]);
    swp(RE[14], RE[15]); swp(IM[14], IM[15]);
    // cnot(4,5): bit0==1 -> swap the two lanes of the pack
#pragma unroll
    for (int K = 1; K < 16; K += 2) {
        RE[K] = lsw(RE[K]);
        IM[K] = lsw(IM[K]);
    }
}

__global__ __launch_bounds__(128, 4)
void qsim_kernel(const float* __restrict__ x, float* __restrict__ out, int B) {
    __shared__ float2 sM[NL * NQ * 4];
    if (threadIdx.x < NL * NQ * 4) sM[threadIdx.x] = g_M[threadIdx.x];
    __syncthreads();
    const ull* sMu = reinterpret_cast<const ull*>(sM);  // (x,y) pairs, 8B-aligned

    int tid = blockIdx.x * blockDim.x + threadIdx.x;
    int b = tid >> 1;
    if (b >= B) return;
    int p = tid & 1;  // this thread's wire-0 (MSB) value

    // Vectorized x load (x + 6*b is 8B-aligned), then angles.
    float cs[NQ], sn[NQ];
    {
        const float2* xx = reinterpret_cast<const float2*>(x + (size_t)b * NQ);
        float2 x01 = xx[0], x23 = xx[1], x45 = xx[2];
        float xv[NQ] = {x01.x, x01.y, x23.x, x23.y, x45.x, x45.y};
#pragma unroll
        for (int q = 0; q < NQ; q++) {
            float t = 1.5707963267948966f * tanh_fast(xv[q]);
            __sincosf(t, &sn[q], &cs[q]);
        }
    }

    // 32 local amps packed: RE[K] = (re_{2K}, re_{2K+1}), pack lane = wire5.
    // Pack-index bits 3..0 = wires 1..4.
    ull RE[16], IM[16];

    // ---- Layer 0: product state |0..0> -> tensor of first gate columns ----
    {
        // wire-0 factor (this thread's row), as an (x,y) pair
        ull A;
        {
            ull ma = p ? sMu[2] : sMu[0];
            ull mb = p ? sMu[3] : sMu[1];
            A = fma2(sp2(cs[0]), ma, mul2(sp2(sn[0]), mb));
        }
        // wire-5 factor, packed across lanes
        {
            ull c2 = sp2(cs[5]), s2 = sp2(sn[5]);
            ull V0 = fma2(c2, sMu[20], mul2(s2, sMu[21]));
            ull V1 = fma2(c2, sMu[22], mul2(s2, sMu[23]));
            ull V5X = pk(flo(V0), flo(V1));
            ull V5Y = pk(fhi(V0), fhi(V1));
            ull V5Yn = neg2(V5Y);
            ull ax2 = sp2(flo(A)), ay2 = sp2(fhi(A));
            RE[0] = fma2(ax2, V5X, mul2(ay2, V5Yn));
            IM[0] = fma2(ax2, V5Y, mul2(ay2, V5X));
        }
#pragma unroll
        for (int q = 1; q <= 4; q++) {
            ull c2 = sp2(cs[q]), s2 = sp2(sn[q]);
            ull V0 = fma2(c2, sMu[q * 4 + 0], mul2(s2, sMu[q * 4 + 1]));
            ull V1 = fma2(c2, sMu[q * 4 + 2], mul2(s2, sMu[q * 4 + 3]));
            ull x0 = sp2(flo(V0)), y0 = sp2(fhi(V0)), ny0 = neg2(y0);
            ull x1 = sp2(flo(V1)), y1 = sp2(fhi(V1)), ny1 = neg2(y1);
            int n = 1 << (q - 1);
#pragma unroll
            for (int k = 15; k >= 0; k--) {
                if (k < n) {
                    ull r = RE[k], i = IM[k];
                    RE[2 * k + 1] = fma2(x1, r, mul2(ny1, i));
                    IM[2 * k + 1] = fma2(x1, i, mul2(y1, r));
                    RE[2 * k]     = fma2(x0, r, mul2(ny0, i));
                    IM[2 * k]     = fma2(x0, i, mul2(y0, r));
                }
            }
        }
    }
    cnot_ring_partial(RE, IM, p);  // cnot(5,0) pending -> fused into next gate_w0

    // ---- Layers 1..2 ----
#pragma unroll
    for (int layer = 1; layer < NL; layer++) {
        const ull* mbase = sMu + layer * NQ * 4;
        ull P00, P01, P10, P11;
        // wire 0 (cross-thread), fused with pending cnot(5,0).
        // Only row p of G is needed: a=m[2p], b=m[2p+1]:
        //   u = c*a + s*b, v = -s*a + c*b; Gd = p?v:u, Go = p?u:v.
        {
            ull ma = p ? mbase[2] : mbase[0];
            ull mb = p ? mbase[3] : mbase[1];
            ull c2 = sp2(cs[0]), s2 = sp2(sn[0]);
            ull U = fma2(c2, ma, mul2(s2, mb));
            ull V = fma2(c2, mb, mul2(neg2(s2), ma));
            ull Gd = p ? V : U;
            ull Go = p ? U : V;
            gate_w0_fused(RE, IM, Gd, Go);
        }
        // wires 1..4 (local packed)
        makeGp(mbase + 4, cs[1], sn[1], P00, P01, P10, P11);
        gate_local<8>(RE, IM, P00, P01, P10, P11);
        makeGp(mbase + 8, cs[2], sn[2], P00, P01, P10, P11);
        gate_local<4>(RE, IM, P00, P01, P10, P11);
        makeGp(mbase + 12, cs[3], sn[3], P00, P01, P10, P11);
        gate_local<2>(RE, IM, P00, P01, P10, P11);
        makeGp(mbase + 16, cs[4], sn[4], P00, P01, P10, P11);
        gate_local<1>(RE, IM, P00, P01, P10, P11);
        // wire 5 (intra-pack, swap-form)
        makeGp(mbase + 20, cs[5], sn[5], P00, P01, P10, P11);
        gate_w5(RE, IM, P00, P01, P10, P11);

        cnot_ring_partial(RE, IM, p);  // cnot(5,0) pending again
    }

    // ---- Readout: Walsh butterfly over pack index (signs = wire bits),
    //      final cnot(5,0) folded into the e0 sign. All values stay packed. ----
    ull PR[16];
#pragma unroll
    for (int K = 0; K < 16; K++) {
        PR[K] = fma2(RE[K], RE[K], mul2(IM[K], IM[K]));
    }
    // level A: bit0 of K = wire4
    ull sA[8], dA[8];
#pragma unroll
    for (int k = 0; k < 8; k++) {
        sA[k] = add2(PR[2 * k], PR[2 * k + 1]);
        dA[k] = add2(PR[2 * k], neg2(PR[2 * k + 1]));
    }
    ull E4 = add2(add2(add2(dA[0], dA[1]), add2(dA[2], dA[3])),
                  add2(add2(dA[4], dA[5]), add2(dA[6], dA[7])));
    // level B: bit1 = wire3
    ull sB[4], dB[4];
#pragma unroll
    for (int k = 0; k < 4; k++) {
        sB[k] = add2(sA[2 * k], sA[2 * k + 1]);
        dB[k] = add2(sA[2 * k], neg2(sA[2 * k + 1]));
    }
    ull E3 = add2(add2(dB[0], dB[1]), add2(dB[2], dB[3]));
    // level C: bit2 = wire2
    ull sC0 = add2(sB[0], sB[1]), sC1 = add2(sB[2], sB[3]);
    ull E2 = add2(add2(sB[0], neg2(sB[1])), add2(sB[2], neg2(sB[3])));
    // level D: bit3 = wire1
    ull At = add2(sC0, sC1);
    ull E1 = add2(sC0, neg2(sC1));

    float dsum = flo(At) - fhi(At);
    float e0 = p ? -dsum : dsum;  // lo lane: wire0 = p; hi lane: wire0 = 1-p
    float e5 = dsum;              // wire5 = lane, unaffected by cnot(5,0)
    float e1 = flo(E1) + fhi(E1);
    float e2 = flo(E2) + fhi(E2);
    float e3 = flo(E3) + fhi(E3);
    float e4 = flo(E4) + fhi(E4);
    e0 += __shfl_xor_sync(0xffffffffu, e0, 1);
    e1 += __shfl_xor_sync(0xffffffffu, e1, 1);
    e2 += __shfl_xor_sync(0xffffffffu, e2, 1);
    e3 += __shfl_xor_sync(0xffffffffu, e3, 1);
    e4 += __shfl_xor_sync(0xffffffffu, e4, 1);
    e5 += __shfl_xor_sync(0xffffffffu, e5, 1);

    float* ob = out + (size_t)b * NQ;
    if (p == 0) {
        ob[0] = e0; ob[1] = e1; ob[2] = e2;
    } else {
        ob[3] = e3; ob[4] = e4; ob[5] = e5;
    }
}

extern "C" void kernel_launch(void* const* d_in, const int* in_sizes, int n_in,
                              void* d_out, int out_size) {
    const float* x = (const float*)d_in[0];
    const float* w = (const float*)d_in[1];
    float* out = (float*)d_out;
    int B = in_sizes[0] / NQ;

    setup_gates<<<1, 32>>>(w);

    const int threads = 128;
    long long total = 2LL * B;
    int blocks = (int)((total + threads - 1) / threads);
    qsim_kernel<<<blocks, threads>>>(x, out, B);
}

// round 8
// speedup vs baseline: 1.1073x; 1.1073x over previous
#include <cuda_runtime.h>

#define NQ 6
#define NL 3

typedef unsigned long long ull;

// Weight-only part of each gate: M = RZ(w2) @ RY(w1) @ RZ(w0), complex 2x2.
__device__ float2 g_M[NL * NQ * 4];

__global__ void setup_gates(const float* __restrict__ w) {
    int g = threadIdx.x;
    if (g >= NL * NQ) return;
    float w0 = w[g * 3 + 0];
    float w1 = w[g * 3 + 1];
    float w2 = w[g * 3 + 2];
    float s1, c1, sp_, cp_, sm2, cm2;
    sincosf(0.5f * w1, &s1, &c1);
    sincosf(0.5f * (w0 + w2), &sp_, &cp_);
    sincosf(0.5f * (w0 - w2), &sm2, &cm2);
    g_M[g * 4 + 0] = make_float2(c1 * cp_, -c1 * sp_);   // M00
    g_M[g * 4 + 1] = make_float2(-s1 * cm2, -s1 * sm2);  // M01
    g_M[g * 4 + 2] = make_float2(s1 * cm2, -s1 * sm2);   // M10
    g_M[g * 4 + 3] = make_float2(c1 * cp_, c1 * sp_);    // M11
}

// ---- packed f32x2 helpers ----
__device__ __forceinline__ ull fma2(ull a, ull b, ull c) {
    ull d; asm("fma.rn.f32x2 %0,%1,%2,%3;" : "=l"(d) : "l"(a), "l"(b), "l"(c)); return d;
}
__device__ __forceinline__ ull mul2(ull a, ull b) {
    ull d; asm("mul.rn.f32x2 %0,%1,%2;" : "=l"(d) : "l"(a), "l"(b)); return d;
}
__device__ __forceinline__ ull add2(ull a, ull b) {
    ull d; asm("add.rn.f32x2 %0,%1,%2;" : "=l"(d) : "l"(a), "l"(b)); return d;
}
__device__ __forceinline__ ull pk(float lo, float hi) {
    ull d; asm("mov.b64 %0,{%1,%2};" : "=l"(d) : "f"(lo), "f"(hi)); return d;
}
__device__ __forceinline__ ull sp2(float x) { return pk(x, x); }
__device__ __forceinline__ float flo(ull v) { return __uint_as_float((unsigned)v); }
__device__ __forceinline__ float fhi(ull v) { return __uint_as_float((unsigned)(v >> 32)); }
__device__ __forceinline__ ull lsw(ull v) { return pk(fhi(v), flo(v)); }     // lane swap
__device__ __forceinline__ ull neg2(ull v) { return v ^ 0x8000000080000000ULL; }
__device__ __forceinline__ float tanh_fast(float x) {
    float y; asm("tanh.approx.f32 %0, %1;" : "=f"(y) : "f"(x)); return y;
}

// Gate on local wire w in {1..4}: pack-index stride S = 1<<(4-w). Element-wise packed.
template <int S>
__device__ __forceinline__ void gate_local(ull* RE, ull* IM,
                                           float2 G00, float2 G01, float2 G10, float2 G11) {
    ull x00 = sp2(G00.x), ny00 = sp2(-G00.y), y00 = sp2(G00.y);
    ull x01 = sp2(G01.x), ny01 = sp2(-G01.y), y01 = sp2(G01.y);
    ull x10 = sp2(G10.x), ny10 = sp2(-G10.y), y10 = sp2(G10.y);
    ull x11 = sp2(G11.x), ny11 = sp2(-G11.y), y11 = sp2(G11.y);
#pragma unroll
    for (int t = 0; t < 8; t++) {
        int K0 = ((t & ~(S - 1)) << 1) | (t & (S - 1));
        int K1 = K0 + S;
        ull r0 = RE[K0], i0 = IM[K0], r1 = RE[K1], i1 = IM[K1];
        RE[K0] = fma2(x00, r0, fma2(ny00, i0, fma2(x01, r1, mul2(ny01, i1))));
        IM[K0] = fma2(x00, i0, fma2(y00, r0, fma2(x01, i1, mul2(y01, r1))));
        RE[K1] = fma2(x10, r0, fma2(ny10, i0, fma2(x11, r1, mul2(ny11, i1))));
        IM[K1] = fma2(x10, i0, fma2(y10, r0, fma2(x11, i1, mul2(y11, r1))));
    }
}

// Gate on wire 5 (the two lanes inside each pack), swap-form:
// out = P .* st + Q .* laneswap(st), P=(G00,G11), Q=(G01,G10).
__device__ __forceinline__ void gate_w5(ull* RE, ull* IM,
                                        float2 G00, float2 G01, float2 G10, float2 G11) {
    ull Px = pk(G00.x, G11.x), Py = pk(G00.y, G11.y), nPy = pk(-G00.y, -G11.y);
    ull Qx = pk(G01.x, G10.x), Qy = pk(G01.y, G10.y), nQy = pk(-G01.y, -G10.y);
#pragma unroll
    for (int K = 0; K < 16; K++) {
        ull r = RE[K], i = IM[K];
        ull rs = lsw(r), is = lsw(i);
        RE[K] = fma2(Px, r, fma2(nPy, i, fma2(Qx, rs, mul2(nQy, is))));
        IM[K] = fma2(Px, i, fma2(Py, r, fma2(Qx, is, mul2(Qy, rs))));
    }
}

// Gate on wire 0 fused with a PENDING cnot(5,0) from the preceding ring.
// The cnot(5,0) lane merge is absorbed into asymmetric coefficient packs:
//   out = pk(Gd,Go) .* mine + pk(Go,Gd) .* partner     (no lane merges needed)
__device__ __forceinline__ void gate_w0_fused(ull* RE, ull* IM, float2 Gd, float2 Go) {
    ull dx = pk(Gd.x, Go.x), ox = pk(Go.x, Gd.x);
    ull dy = pk(Gd.y, Go.y), oy = pk(Go.y, Gd.y);
    ull ndy = pk(-Gd.y, -Go.y), noy = pk(-Go.y, -Gd.y);
#pragma unroll
    for (int K = 0; K < 16; K++) {
        ull pr = __shfl_xor_sync(0xffffffffu, RE[K], 1);
        ull pi = __shfl_xor_sync(0xffffffffu, IM[K], 1);
        ull r = RE[K], i = IM[K];
        RE[K] = fma2(dx, r, fma2(ndy, i, fma2(ox, pr, mul2(noy, pi))));
        IM[K] = fma2(dx, i, fma2(dy, r, fma2(ox, pi, mul2(oy, pr))));
    }
}

__device__ __forceinline__ void swp(ull& a, ull& b) { ull t = a; a = b; b = t; }

// CNOT ring WITHOUT the final cnot(5,0): (0,1)(1,2)(2,3)(3,4)(4,5).
// The trailing cnot(5,0) is fused into the next wire-0 gate (or readout).
__device__ __forceinline__ void cnot_ring_partial(ull* RE, ull* IM, int p) {
    // cnot(0,1): p==1 threads flip pack bit3
    {
        bool pb = (p != 0);
#pragma unroll
        for (int K = 0; K < 8; K++) {
            ull a = RE[K], b = RE[K + 8];
            RE[K] = pb ? b : a; RE[K + 8] = pb ? a : b;
            ull c = IM[K], d = IM[K + 8];
            IM[K] = pb ? d : c; IM[K + 8] = pb ? c : d;
        }
    }
    // cnot(1,2): bit3==1 -> flip bit2  (free renames)
    swp(RE[8], RE[12]); swp(IM[8], IM[12]);
    swp(RE[9], RE[13]); swp(IM[9], IM[13]);
    swp(RE[10], RE[14]); swp(IM[10], IM[14]);
    swp(RE[11], RE[15]); swp(IM[11], IM[15]);
    // cnot(2,3): bit2==1 -> flip bit1
    swp(RE[4], RE[6]);  swp(IM[4], IM[6]);
    swp(RE[5], RE[7]);  swp(IM[5], IM[7]);
    swp(RE[12], RE[14]); swp(IM[12], IM[14]);
    swp(RE[13], RE[15]); swp(IM[13], IM[15]);
    // cnot(3,4): bit1==1 -> flip bit0
    swp(RE[2], RE[3]);  swp(IM[2], IM[3]);
    swp(RE[6], RE[7]);  swp(IM[6], IM[7]);
    swp(RE[10], RE[11]); swp(IM[10], IM[11]);
    swp(RE[14], RE[15]); swp(IM[14], IM[15]);
    // cnot(4,5): bit0==1 -> swap the two lanes of the pack
#pragma unroll
    for (int K = 1; K < 16; K += 2) {
        RE[K] = lsw(RE[K]);
        IM[K] = lsw(IM[K]);
    }
}

__device__ __forceinline__ void makeG(const float2* m, float c, float s,
                                      float2& G00, float2& G01, float2& G10, float2& G11) {
    float2 m00 = m[0], m01 = m[1], m10 = m[2], m11 = m[3];
    G00.x = fmaf(c, m00.x, s * m01.x);  G00.y = fmaf(c, m00.y, s * m01.y);
    G01.x = fmaf(-s, m00.x, c * m01.x); G01.y = fmaf(-s, m00.y, c * m01.y);
    G10.x = fmaf(c, m10.x, s * m11.x);  G10.y = fmaf(c, m10.y, s * m11.y);
    G11.x = fmaf(-s, m10.x, c * m11.x); G11.y = fmaf(-s, m10.y, c * m11.y);
}

__global__ __launch_bounds__(128, 4)
void qsim_kernel(const float* __restrict__ x, float* __restrict__ out, int B) {
    __shared__ float2 sM[NL * NQ * 4];
    if (threadIdx.x < NL * NQ * 4) sM[threadIdx.x] = g_M[threadIdx.x];
    __syncthreads();

    int tid = blockIdx.x * blockDim.x + threadIdx.x;
    int b = tid >> 1;
    if (b >= B) return;
    int p = tid & 1;  // this thread's wire-0 (MSB) value

    // Vectorized x load (x + 6*b is 8B-aligned), then angles.
    float cs[NQ], sn[NQ];
    {
        const float2* xx = reinterpret_cast<const float2*>(x + (size_t)b * NQ);
        float2 x01 = xx[0], x23 = xx[1], x45 = xx[2];
        float xv[NQ] = {x01.x, x01.y, x23.x, x23.y, x45.x, x45.y};
#pragma unroll
        for (int q = 0; q < NQ; q++) {
            float t = 1.5707963267948966f * tanh_fast(xv[q]);
            __sincosf(t, &sn[q], &cs[q]);
        }
    }

    // 32 local amps packed: RE[K] = (re_{2K}, re_{2K+1}), pack lane = wire5.
    // Pack-index bits 3..0 = wires 1..4.
    ull RE[16], IM[16];

    // ---- Layer 0: product state |0..0> -> tensor of first gate columns ----
    {
        float2 a;  // wire-0 factor for this thread
        {
            float2 ma = p ? sM[2] : sM[0];
            float2 mb = p ? sM[3] : sM[1];
            a.x = fmaf(cs[0], ma.x, sn[0] * mb.x);
            a.y = fmaf(cs[0], ma.y, sn[0] * mb.y);
        }
        {
            float2 m00 = sM[5 * 4 + 0], m01 = sM[5 * 4 + 1];
            float2 m10 = sM[5 * 4 + 2], m11 = sM[5 * 4 + 3];
            float2 v0 = make_float2(fmaf(cs[5], m00.x, sn[5] * m01.x),
                                    fmaf(cs[5], m00.y, sn[5] * m01.y));
            float2 v1 = make_float2(fmaf(cs[5], m10.x, sn[5] * m11.x),
                                    fmaf(cs[5], m10.y, sn[5] * m11.y));
            ull V5X = pk(v0.x, v1.x), V5Y = pk(v0.y, v1.y), V5Yn = pk(-v0.y, -v1.y);
            RE[0] = fma2(sp2(a.x), V5X, mul2(sp2(a.y), V5Yn));
            IM[0] = fma2(sp2(a.x), V5Y, mul2(sp2(a.y), V5X));
        }
#pragma unroll
        for (int q = 1; q <= 4; q++) {
            float2 m00 = sM[q * 4 + 0], m01 = sM[q * 4 + 1];
            float2 m10 = sM[q * 4 + 2], m11 = sM[q * 4 + 3];
            float2 v0 = make_float2(fmaf(cs[q], m00.x, sn[q] * m01.x),
                                    fmaf(cs[q], m00.y, sn[q] * m01.y));
            float2 v1 = make_float2(fmaf(cs[q], m10.x, sn[q] * m11.x),
                                    fmaf(cs[q], m10.y, sn[q] * m11.y));
            ull x0 = sp2(v0.x), ny0 = sp2(-v0.y), y0 = sp2(v0.y);
            ull x1 = sp2(v1.x), ny1 = sp2(-v1.y), y1 = sp2(v1.y);
            int n = 1 << (q - 1);
#pragma unroll
            for (int k = 15; k >= 0; k--) {
                if (k < n) {
                    ull r = RE[k], i = IM[k];
                    RE[2 * k + 1] = fma2(x1, r, mul2(ny1, i));
                    IM[2 * k + 1] = fma2(x1, i, mul2(y1, r));
                    RE[2 * k]     = fma2(x0, r, mul2(ny0, i));
                    IM[2 * k]     = fma2(x0, i, mul2(y0, r));
                }
            }
        }
    }
    cnot_ring_partial(RE, IM, p);  // cnot(5,0) pending -> fused into next gate_w0

    // ---- Layers 1..2 ----
#pragma unroll
    for (int layer = 1; layer < NL; layer++) {
        const float2* mbase = &sM[layer * NQ * 4];
        float2 G00, G01, G10, G11;
        // wire 0 (cross-thread), fused with pending cnot(5,0).
        // Only row p of G is needed: from row entries a=m[2p], b=m[2p+1]:
        //   u = c*a + s*b, v = -s*a + c*b; Gd = p?v:u, Go = p?u:v.
        {
            float2 ma = p ? mbase[2] : mbase[0];
            float2 mb = p ? mbase[3] : mbase[1];
            float c = cs[0], s = sn[0];
            float2 u = make_float2(fmaf(c, ma.x, s * mb.x), fmaf(c, ma.y, s * mb.y));
            float2 v = make_float2(fmaf(-s, ma.x, c * mb.x), fmaf(-s, ma.y, c * mb.y));
            float2 Gd = p ? v : u;
            float2 Go = p ? u : v;
            gate_w0_fused(RE, IM, Gd, Go);
        }
        // wires 1..4 (local packed)
        makeG(mbase + 4, cs[1], sn[1], G00, G01, G10, G11);
        gate_local<8>(RE, IM, G00, G01, G10, G11);
        makeG(mbase + 8, cs[2], sn[2], G00, G01, G10, G11);
        gate_local<4>(RE, IM, G00, G01, G10, G11);
        makeG(mbase + 12, cs[3], sn[3], G00, G01, G10, G11);
        gate_local<2>(RE, IM, G00, G01, G10, G11);
        makeG(mbase + 16, cs[4], sn[4], G00, G01, G10, G11);
        gate_local<1>(RE, IM, G00, G01, G10, G11);
        // wire 5 (intra-pack, swap-form)
        makeG(mbase + 20, cs[5], sn[5], G00, G01, G10, G11);
        gate_w5(RE, IM, G00, G01, G10, G11);

        cnot_ring_partial(RE, IM, p);  // cnot(5,0) pending again
    }

    // ---- Readout: Walsh butterfly over pack index (signs = wire bits),
    //      final cnot(5,0) folded into the e0 sign. All values stay packed. ----
    ull PR[16];
#pragma unroll
    for (int K = 0; K < 16; K++) {
        PR[K] = fma2(RE[K], RE[K], mul2(IM[K], IM[K]));
    }
    // level A: bit0 of K = wire4
    ull sA[8], dA[8];
#pragma unroll
    for (int k = 0; k < 8; k++) {
        sA[k] = add2(PR[2 * k], PR[2 * k + 1]);
        dA[k] = add2(PR[2 * k], neg2(PR[2 * k + 1]));
    }
    ull E4 = add2(add2(add2(dA[0], dA[1]), add2(dA[2], dA[3])),
                  add2(add2(dA[4], dA[5]), add2(dA[6], dA[7])));
    // level B: bit1 = wire3
    ull sB[4], dB[4];
#pragma unroll
    for (int k = 0; k < 4; k++) {
        sB[k] = add2(sA[2 * k], sA[2 * k + 1]);
        dB[k] = add2(sA[2 * k], neg2(sA[2 * k + 1]));
    }
    ull E3 = add2(add2(dB[0], dB[1]), add2(dB[2], dB[3]));
    // level C: bit2 = wire2
    ull sC0 = add2(sB[0], sB[1]), sC1 = add2(sB[2], sB[3]);
    ull E2 = add2(add2(sB[0], neg2(sB[1])), add2(sB[2], neg2(sB[3])));
    // level D: bit3 = wire1
    ull At = add2(sC0, sC1);
    ull E1 = add2(sC0, neg2(sC1));

    float dsum = flo(At) - fhi(At);
    float e0 = p ? -dsum : dsum;  // lo lane: wire0 = p; hi lane: wire0 = 1-p
    float e5 = dsum;              // wire5 = lane, unaffected by cnot(5,0)
    float e1 = flo(E1) + fhi(E1);
    float e2 = flo(E2) + fhi(E2);
    float e3 = flo(E3) + fhi(E3);
    float e4 = flo(E4) + fhi(E4);
    e0 += __shfl_xor_sync(0xffffffffu, e0, 1);
    e1 += __shfl_xor_sync(0xffffffffu, e1, 1);
    e2 += __shfl_xor_sync(0xffffffffu, e2, 1);
    e3 += __shfl_xor_sync(0xffffffffu, e3, 1);
    e4 += __shfl_xor_sync(0xffffffffu, e4, 1);
    e5 += __shfl_xor_sync(0xffffffffu, e5, 1);

    // Vectorized stores: b*6 floats = 24B base (8B-aligned).
    float* ob = out + (size_t)b * NQ;
    if (p == 0) {
        *reinterpret_cast<float2*>(ob) = make_float2(e0, e1);  // ob[0..1]
        ob[2] = e2;
    } else {
        ob[3] = e3;
        *reinterpret_cast<float2*>(ob + 4) = make_float2(e4, e5);  // ob[4..5]
    }
}

extern "C" void kernel_launch(void* const* d_in, const int* in_sizes, int n_in,
                              void* d_out, int out_size) {
    const float* x = (const float*)d_in[0];
    const float* w = (const float*)d_in[1];
    float* out = (float*)d_out;
    int B = in_sizes[0] / NQ;

    setup_gates<<<1, 32>>>(w);

    const int threads = 128;
    long long total = 2LL * B;
    int blocks = (int)((total + threads - 1) / threads);
    qsim_kernel<<<blocks, threads>>>(x, out, B);
}

// round 9
// speedup vs baseline: 1.1078x; 1.0005x over previous
#include <cuda_runtime.h>

#define NQ 6
#define NL 3

typedef unsigned long long ull;

// Weight-only part of each gate: M = RZ(w2) @ RY(w1) @ RZ(w0), complex 2x2.
__device__ float2 g_M[NL * NQ * 4];

__global__ void setup_gates(const float* __restrict__ w) {
    int g = threadIdx.x;
    if (g >= NL * NQ) return;
    float w0 = w[g * 3 + 0];
    float w1 = w[g * 3 + 1];
    float w2 = w[g * 3 + 2];
    float s1, c1, sp_, cp_, sm2, cm2;
    sincosf(0.5f * w1, &s1, &c1);
    sincosf(0.5f * (w0 + w2), &sp_, &cp_);
    sincosf(0.5f * (w0 - w2), &sm2, &cm2);
    g_M[g * 4 + 0] = make_float2(c1 * cp_, -c1 * sp_);   // M00
    g_M[g * 4 + 1] = make_float2(-s1 * cm2, -s1 * sm2);  // M01
    g_M[g * 4 + 2] = make_float2(s1 * cm2, -s1 * sm2);   // M10
    g_M[g * 4 + 3] = make_float2(c1 * cp_, c1 * sp_);    // M11
}

// ---- packed f32x2 helpers ----
__device__ __forceinline__ ull fma2(ull a, ull b, ull c) {
    ull d; asm("fma.rn.f32x2 %0,%1,%2,%3;" : "=l"(d) : "l"(a), "l"(b), "l"(c)); return d;
}
__device__ __forceinline__ ull mul2(ull a, ull b) {
    ull d; asm("mul.rn.f32x2 %0,%1,%2;" : "=l"(d) : "l"(a), "l"(b)); return d;
}
__device__ __forceinline__ ull add2(ull a, ull b) {
    ull d; asm("add.rn.f32x2 %0,%1,%2;" : "=l"(d) : "l"(a), "l"(b)); return d;
}
__device__ __forceinline__ ull pk(float lo, float hi) {
    ull d; asm("mov.b64 %0,{%1,%2};" : "=l"(d) : "f"(lo), "f"(hi)); return d;
}
__device__ __forceinline__ ull sp2(float x) { return pk(x, x); }
__device__ __forceinline__ float flo(ull v) { return __uint_as_float((unsigned)v); }
__device__ __forceinline__ float fhi(ull v) { return __uint_as_float((unsigned)(v >> 32)); }
__device__ __forceinline__ ull lsw(ull v) { return pk(fhi(v), flo(v)); }     // lane swap
__device__ __forceinline__ ull neg2(ull v) { return v ^ 0x8000000080000000ULL; }
__device__ __forceinline__ float tanh_fast(float x) {
    float y; asm("tanh.approx.f32 %0, %1;" : "=f"(y) : "f"(x)); return y;
}

// Gate on local wire w in {1..4}: pack-index stride S = 1<<(4-w).
// 2-way interleaved, coefficient-slot-major ordering: each coefficient feeds
// two consecutive instructions in the same operand slot -> operand-reuse cache
// eliminates the repeated RF-bank read (rt 3 -> 2 on the second op).
template <int S>
__device__ __forceinline__ void gate_local(ull* RE, ull* IM,
                                           float2 G00, float2 G01, float2 G10, float2 G11) {
    ull x00 = sp2(G00.x), ny00 = sp2(-G00.y), y00 = sp2(G00.y);
    ull x01 = sp2(G01.x), ny01 = sp2(-G01.y), y01 = sp2(G01.y);
    ull x10 = sp2(G10.x), ny10 = sp2(-G10.y), y10 = sp2(G10.y);
    ull x11 = sp2(G11.x), ny11 = sp2(-G11.y), y11 = sp2(G11.y);
#pragma unroll
    for (int t = 0; t < 8; t += 2) {
        const int u = t + 1;
        const int A0 = ((t & ~(S - 1)) << 1) | (t & (S - 1));
        const int A1 = A0 + S;
        const int B0 = ((u & ~(S - 1)) << 1) | (u & (S - 1));
        const int B1 = B0 + S;
        ull r0a = RE[A0], i0a = IM[A0], r1a = RE[A1], i1a = IM[A1];
        ull r0b = RE[B0], i0b = IM[B0], r1b = RE[B1], i1b = IM[B1];
        // new RE[.0]
        ull pa = mul2(ny01, i1a);        ull pb = mul2(ny01, i1b);
        pa = fma2(x01, r1a, pa);         pb = fma2(x01, r1b, pb);
        pa = fma2(ny00, i0a, pa);        pb = fma2(ny00, i0b, pb);
        pa = fma2(x00, r0a, pa);         pb = fma2(x00, r0b, pb);
        // new IM[.0]
        ull qa = mul2(y01, r1a);         ull qb = mul2(y01, r1b);
        qa = fma2(x01, i1a, qa);         qb = fma2(x01, i1b, qb);
        qa = fma2(y00, r0a, qa);         qb = fma2(y00, r0b, qb);
        qa = fma2(x00, i0a, qa);         qb = fma2(x00, i0b, qb);
        // new RE[.1]
        ull ra = mul2(ny11, i1a);        ull rb = mul2(ny11, i1b);
        ra = fma2(x11, r1a, ra);         rb = fma2(x11, r1b, rb);
        ra = fma2(ny10, i0a, ra);        rb = fma2(ny10, i0b, rb);
        ra = fma2(x10, r0a, ra);         rb = fma2(x10, r0b, rb);
        // new IM[.1]
        ull sa = mul2(y11, r1a);         ull sb = mul2(y11, r1b);
        sa = fma2(x11, i1a, sa);         sb = fma2(x11, i1b, sb);
        sa = fma2(y10, r0a, sa);         sb = fma2(y10, r0b, sb);
        sa = fma2(x10, i0a, sa);         sb = fma2(x10, i0b, sb);
        RE[A0] = pa; RE[B0] = pb; IM[A0] = qa; IM[B0] = qb;
        RE[A1] = ra; RE[B1] = rb; IM[A1] = sa; IM[B1] = sb;
    }
}

// Gate on wire 5 (the two lanes inside each pack), swap-form, 2-way interleaved.
__device__ __forceinline__ void gate_w5(ull* RE, ull* IM,
                                        float2 G00, float2 G01, float2 G10, float2 G11) {
    ull Px = pk(G00.x, G11.x), Py = pk(G00.y, G11.y), nPy = pk(-G00.y, -G11.y);
    ull Qx = pk(G01.x, G10.x), Qy = pk(G01.y, G10.y), nQy = pk(-G01.y, -G10.y);
#pragma unroll
    for (int K = 0; K < 16; K += 2) {
        ull ra = RE[K], ia = IM[K], rb = RE[K + 1], ib = IM[K + 1];
        ull rsa = lsw(ra), isa = lsw(ia), rsb = lsw(rb), isb = lsw(ib);
        ull pa = mul2(nQy, isa);         ull pb = mul2(nQy, isb);
        pa = fma2(Qx, rsa, pa);          pb = fma2(Qx, rsb, pb);
        pa = fma2(nPy, ia, pa);          pb = fma2(nPy, ib, pb);
        pa = fma2(Px, ra, pa);           pb = fma2(Px, rb, pb);
        ull qa = mul2(Qy, rsa);          ull qb = mul2(Qy, rsb);
        qa = fma2(Qx, isa, qa);          qb = fma2(Qx, isb, qb);
        qa = fma2(Py, ra, qa);           qb = fma2(Py, rb, qb);
        qa = fma2(Px, ia, qa);           qb = fma2(Px, ib, qb);
        RE[K] = pa; RE[K + 1] = pb; IM[K] = qa; IM[K + 1] = qb;
    }
}

// Gate on wire 0 fused with a PENDING cnot(5,0); 2-way interleaved.
__device__ __forceinline__ void gate_w0_fused(ull* RE, ull* IM, float2 Gd, float2 Go) {
    ull dx = pk(Gd.x, Go.x), ox = pk(Go.x, Gd.x);
    ull dy = pk(Gd.y, Go.y), oy = pk(Go.y, Gd.y);
    ull ndy = pk(-Gd.y, -Go.y), noy = pk(-Go.y, -Gd.y);
#pragma unroll
    for (int K = 0; K < 16; K += 2) {
        ull pra = __shfl_xor_sync(0xffffffffu, RE[K], 1);
        ull pia = __shfl_xor_sync(0xffffffffu, IM[K], 1);
        ull prb = __shfl_xor_sync(0xffffffffu, RE[K + 1], 1);
        ull pib = __shfl_xor_sync(0xffffffffu, IM[K + 1], 1);
        ull ra = RE[K], ia = IM[K], rb = RE[K + 1], ib = IM[K + 1];
        ull ua = mul2(noy, pia);         ull ub = mul2(noy, pib);
        ua = fma2(ox, pra, ua);          ub = fma2(ox, prb, ub);
        ua = fma2(ndy, ia, ua);          ub = fma2(ndy, ib, ub);
        ua = fma2(dx, ra, ua);           ub = fma2(dx, rb, ub);
        ull va = mul2(oy, pra);          ull vb = mul2(oy, prb);
        va = fma2(ox, pia, va);          vb = fma2(ox, pib, vb);
        va = fma2(dy, ra, va);           vb = fma2(dy, rb, vb);
        va = fma2(dx, ia, va);           vb = fma2(dx, ib, vb);
        RE[K] = ua; RE[K + 1] = ub; IM[K] = va; IM[K + 1] = vb;
    }
}

__device__ __forceinline__ void swp(ull& a, ull& b) { ull t = a; a = b; b = t; }

// CNOT ring WITHOUT the final cnot(5,0): (0,1)(1,2)(2,3)(3,4)(4,5).
__device__ __forceinline__ void cnot_ring_partial(ull* RE, ull* IM, int p) {
    // cnot(0,1): p==1 threads flip pack bit3
    {
        bool pb = (p != 0);
#pragma unroll
        for (int K = 0; K < 8; K++) {
            ull a = RE[K], b = RE[K + 8];
            RE[K] = pb ? b : a; RE[K + 8] = pb ? a : b;
            ull c = IM[K], d = IM[K + 8];
            IM[K] = pb ? d : c; IM[K + 8] = pb ? c : d;
        }
    }
    // cnot(1,2): bit3==1 -> flip bit2  (free renames)
    swp(RE[8], RE[12]); swp(IM[8], IM[12]);
    swp(RE[9], RE[13]); swp(IM[9], IM[13]);
    swp(RE[10], RE[14]); swp(IM[10], IM[14]);
    swp(RE[11], RE[15]); swp(IM[11], IM[15]);
    // cnot(2,3): bit2==1 -> flip bit1
    swp(RE[4], RE[6]);  swp(IM[4], IM[6]);
    swp(RE[5], RE[7]);  swp(IM[5], IM[7]);
    swp(RE[12], RE[14]); swp(IM[12], IM[14]);
    swp(RE[13], RE[15]); swp(IM[13], IM[15]);
    // cnot(3,4): bit1==1 -> flip bit0
    swp(RE[2], RE[3]);  swp(IM[2], IM[3]);
    swp(RE[6], RE[7]);  swp(IM[6], IM[7]);
    swp(RE[10], RE[11]); swp(IM[10], IM[11]);
    swp(RE[14], RE[15]); swp(IM[14], IM[15]);
    // cnot(4,5): bit0==1 -> swap the two lanes of the pack
#pragma unroll
    for (int K = 1; K < 16; K += 2) {
        RE[K] = lsw(RE[K]);
        IM[K] = lsw(IM[K]);
    }
}

__device__ __forceinline__ void makeG(const float2* m, float c, float s,
                                      float2& G00, float2& G01, float2& G10, float2& G11) {
    float2 m00 = m[0], m01 = m[1], m10 = m[2], m11 = m[3];
    G00.x = fmaf(c, m00.x, s * m01.x);  G00.y = fmaf(c, m00.y, s * m01.y);
    G01.x = fmaf(-s, m00.x, c * m01.x); G01.y = fmaf(-s, m00.y, c * m01.y);
    G10.x = fmaf(c, m10.x, s * m11.x);  G10.y = fmaf(c, m10.y, s * m11.y);
    G11.x = fmaf(-s, m10.x, c * m11.x); G11.y = fmaf(-s, m10.y, c * m11.y);
}

__global__ __launch_bounds__(128, 4)
void qsim_kernel(const float* __restrict__ x, float* __restrict__ out, int B) {
    __shared__ float2 sM[NL * NQ * 4];
    if (threadIdx.x < NL * NQ * 4) sM[threadIdx.x] = g_M[threadIdx.x];
    __syncthreads();

    int tid = blockIdx.x * blockDim.x + threadIdx.x;
    int b = tid >> 1;
    if (b >= B) return;
    int p = tid & 1;  // this thread's wire-0 (MSB) value

    // Vectorized x load (x + 6*b is 8B-aligned), then angles.
    float cs[NQ], sn[NQ];
    {
        const float2* xx = reinterpret_cast<const float2*>(x + (size_t)b * NQ);
        float2 x01 = xx[0], x23 = xx[1], x45 = xx[2];
        float xv[NQ] = {x01.x, x01.y, x23.x, x23.y, x45.x, x45.y};
#pragma unroll
        for (int q = 0; q < NQ; q++) {
            float t = 1.5707963267948966f * tanh_fast(xv[q]);
            __sincosf(t, &sn[q], &cs[q]);
        }
    }

    // 32 local amps packed: RE[K] = (re_{2K}, re_{2K+1}), pack lane = wire5.
    // Pack-index bits 3..0 = wires 1..4.
    ull RE[16], IM[16];

    // ---- Layer 0: product state |0..0> -> tensor of first gate columns ----
    {
        float2 a;  // wire-0 factor for this thread
        {
            float2 ma = p ? sM[2] : sM[0];
            float2 mb = p ? sM[3] : sM[1];
            a.x = fmaf(cs[0], ma.x, sn[0] * mb.x);
            a.y = fmaf(cs[0], ma.y, sn[0] * mb.y);
        }
        {
            float2 m00 = sM[5 * 4 + 0], m01 = sM[5 * 4 + 1];
            float2 m10 = sM[5 * 4 + 2], m11 = sM[5 * 4 + 3];
            float2 v0 = make_float2(fmaf(cs[5], m00.x, sn[5] * m01.x),
                                    fmaf(cs[5], m00.y, sn[5] * m01.y));
            float2 v1 = make_float2(fmaf(cs[5], m10.x, sn[5] * m11.x),
                                    fmaf(cs[5], m10.y, sn[5] * m11.y));
            ull V5X = pk(v0.x, v1.x), V5Y = pk(v0.y, v1.y), V5Yn = pk(-v0.y, -v1.y);
            RE[0] = fma2(sp2(a.x), V5X, mul2(sp2(a.y), V5Yn));
            IM[0] = fma2(sp2(a.x), V5Y, mul2(sp2(a.y), V5X));
        }
#pragma unroll
        for (int q = 1; q <= 4; q++) {
            float2 m00 = sM[q * 4 + 0], m01 = sM[q * 4 + 1];
            float2 m10 = sM[q * 4 + 2], m11 = sM[q * 4 + 3];
            float2 v0 = make_float2(fmaf(cs[q], m00.x, sn[q] * m01.x),
                                    fmaf(cs[q], m00.y, sn[q] * m01.y));
            float2 v1 = make_float2(fmaf(cs[q], m10.x, sn[q] * m11.x),
                                    fmaf(cs[q], m10.y, sn[q] * m11.y));
            ull x0 = sp2(v0.x), ny0 = sp2(-v0.y), y0 = sp2(v0.y);
            ull x1 = sp2(v1.x), ny1 = sp2(-v1.y), y1 = sp2(v1.y);
            int n = 1 << (q - 1);
#pragma unroll
            for (int k = 15; k >= 0; k--) {
                if (k < n) {
                    ull r = RE[k], i = IM[k];
                    RE[2 * k + 1] = fma2(x1, r, mul2(ny1, i));
                    IM[2 * k + 1] = fma2(x1, i, mul2(y1, r));
                    RE[2 * k]     = fma2(x0, r, mul2(ny0, i));
                    IM[2 * k]     = fma2(x0, i, mul2(y0, r));
                }
            }
        }
    }
    cnot_ring_partial(RE, IM, p);  // cnot(5,0) pending -> fused into next gate_w0

    // ---- Layers 1..2 ----
#pragma unroll
    for (int layer = 1; layer < NL; layer++) {
        const float2* mbase = &sM[layer * NQ * 4];
        float2 G00, G01, G10, G11;
        // wire 0 (cross-thread), fused with pending cnot(5,0).
        {
            float2 ma = p ? mbase[2] : mbase[0];
            float2 mb = p ? mbase[3] : mbase[1];
            float c = cs[0], s = sn[0];
            float2 u = make_float2(fmaf(c, ma.x, s * mb.x), fmaf(c, ma.y, s * mb.y));
            float2 v = make_float2(fmaf(-s, ma.x, c * mb.x), fmaf(-s, ma.y, c * mb.y));
            float2 Gd = p ? v : u;
            float2 Go = p ? u : v;
            gate_w0_fused(RE, IM, Gd, Go);
        }
        // wires 1..4 (local packed)
        makeG(mbase + 4, cs[1], sn[1], G00, G01, G10, G11);
        gate_local<8>(RE, IM, G00, G01, G10, G11);
        makeG(mbase + 8, cs[2], sn[2], G00, G01, G10, G11);
        gate_local<4>(RE, IM, G00, G01, G10, G11);
        makeG(mbase + 12, cs[3], sn[3], G00, G01, G10, G11);
        gate_local<2>(RE, IM, G00, G01, G10, G11);
        makeG(mbase + 16, cs[4], sn[4], G00, G01, G10, G11);
        gate_local<1>(RE, IM, G00, G01, G10, G11);
        // wire 5 (intra-pack, swap-form)
        makeG(mbase + 20, cs[5], sn[5], G00, G01, G10, G11);
        gate_w5(RE, IM, G00, G01, G10, G11);

        cnot_ring_partial(RE, IM, p);  // cnot(5,0) pending again
    }

    // ---- Readout: Walsh butterfly over pack index (signs = wire bits),
    //      final cnot(5,0) folded into the e0 sign. All values stay packed. ----
    ull PR[16];
#pragma unroll
    for (int K = 0; K < 16; K++) {
        PR[K] = fma2(RE[K], RE[K], mul2(IM[K], IM[K]));
    }
    // level A: bit0 of K = wire4
    ull sA[8], dA[8];
#pragma unroll
    for (int k = 0; k < 8; k++) {
        sA[k] = add2(PR[2 * k], PR[2 * k + 1]);
        dA[k] = add2(PR[2 * k], neg2(PR[2 * k + 1]));
    }
    ull E4 = add2(add2(add2(dA[0], dA[1]), add2(dA[2], dA[3])),
                  add2(add2(dA[4], dA[5]), add2(dA[6], dA[7])));
    // level B: bit1 = wire3
    ull sB[4], dB[4];
#pragma unroll
    for (int k = 0; k < 4; k++) {
        sB[k] = add2(sA[2 * k], sA[2 * k + 1]);
        dB[k] = add2(sA[2 * k], neg2(sA[2 * k + 1]));
    }
    ull E3 = add2(add2(dB[0], dB[1]), add2(dB[2], dB[3]));
    // level C: bit2 = wire2
    ull sC0 = add2(sB[0], sB[1]), sC1 = add2(sB[2], sB[3]);
    ull E2 = add2(add2(sB[0], neg2(sB[1])), add2(sB[2], neg2(sB[3])));
    // level D: bit3 = wire1
    ull At = add2(sC0, sC1);
    ull E1 = add2(sC0, neg2(sC1));

    float dsum = flo(At) - fhi(At);
    float e0 = p ? -dsum : dsum;  // lo lane: wire0 = p; hi lane: wire0 = 1-p
    float e5 = dsum;              // wire5 = lane, unaffected by cnot(5,0)
    float e1 = flo(E1) + fhi(E1);
    float e2 = flo(E2) + fhi(E2);
    float e3 = flo(E3) + fhi(E3);
    float e4 = flo(E4) + fhi(E4);
    e0 += __shfl_xor_sync(0xffffffffu, e0, 1);
    e1 += __shfl_xor_sync(0xffffffffu, e1, 1);
    e2 += __shfl_xor_sync(0xffffffffu, e2, 1);
    e3 += __shfl_xor_sync(0xffffffffu, e3, 1);
    e4 += __shfl_xor_sync(0xffffffffu, e4, 1);
    e5 += __shfl_xor_sync(0xffffffffu, e5, 1);

    // Vectorized stores: b*6 floats = 24B base (8B-aligned).
    float* ob = out + (size_t)b * NQ;
    if (p == 0) {
        *reinterpret_cast<float2*>(ob) = make_float2(e0, e1);  // ob[0..1]
        ob[2] = e2;
    } else {
        ob[3] = e3;
        *reinterpret_cast<float2*>(ob + 4) = make_float2(e4, e5);  // ob[4..5]
    }
}

extern "C" void kernel_launch(void* const* d_in, const int* in_sizes, int n_in,
                              void* d_out, int out_size) {
    const float* x = (const float*)d_in[0];
    const float* w = (const float*)d_in[1];
    float* out = (float*)d_out;
    int B = in_sizes[0] / NQ;

    setup_gates<<<1, 32>>>(w);

    const int threads = 128;
    long long total = 2LL * B;
    int blocks = (int)((total + threads - 1) / threads);
    qsim_kernel<<<blocks, threads>>>(x, out, B);
}

// round 10
// speedup vs baseline: 1.1154x; 1.0069x over previous
#include <cuda_runtime.h>

#define NQ 6
#define NL 3

typedef unsigned long long ull;

// Weight-only part of each gate: M = RZ(w2) @ RY(w1) @ RZ(w0), complex 2x2.
__device__ float2 g_M[NL * NQ * 4];

__global__ void setup_gates(const float* __restrict__ w) {
    int g = threadIdx.x;
    if (g >= NL * NQ) return;
    float w0 = w[g * 3 + 0];
    float w1 = w[g * 3 + 1];
    float w2 = w[g * 3 + 2];
    float s1, c1, sp_, cp_, sm2, cm2;
    sincosf(0.5f * w1, &s1, &c1);
    sincosf(0.5f * (w0 + w2), &sp_, &cp_);
    sincosf(0.5f * (w0 - w2), &sm2, &cm2);
    g_M[g * 4 + 0] = make_float2(c1 * cp_, -c1 * sp_);   // M00
    g_M[g * 4 + 1] = make_float2(-s1 * cm2, -s1 * sm2);  // M01
    g_M[g * 4 + 2] = make_float2(s1 * cm2, -s1 * sm2);   // M10
    g_M[g * 4 + 3] = make_float2(c1 * cp_, c1 * sp_);    // M11
}

// ---- packed f32x2 helpers ----
__device__ __forceinline__ ull fma2(ull a, ull b, ull c) {
    ull d; asm("fma.rn.f32x2 %0,%1,%2,%3;" : "=l"(d) : "l"(a), "l"(b), "l"(c)); return d;
}
__device__ __forceinline__ ull mul2(ull a, ull b) {
    ull d; asm("mul.rn.f32x2 %0,%1,%2;" : "=l"(d) : "l"(a), "l"(b)); return d;
}
__device__ __forceinline__ ull add2(ull a, ull b) {
    ull d; asm("add.rn.f32x2 %0,%1,%2;" : "=l"(d) : "l"(a), "l"(b)); return d;
}
__device__ __forceinline__ ull pk(float lo, float hi) {
    ull d; asm("mov.b64 %0,{%1,%2};" : "=l"(d) : "f"(lo), "f"(hi)); return d;
}
__device__ __forceinline__ ull sp2(float x) { return pk(x, x); }
__device__ __forceinline__ float flo(ull v) { return __uint_as_float((unsigned)v); }
__device__ __forceinline__ float fhi(ull v) { return __uint_as_float((unsigned)(v >> 32)); }
__device__ __forceinline__ ull lsw(ull v) { return pk(fhi(v), flo(v)); }     // lane swap
__device__ __forceinline__ ull neg2(ull v) { return v ^ 0x8000000080000000ULL; }
__device__ __forceinline__ float tanh_fast(float x) {
    float y; asm("tanh.approx.f32 %0, %1;" : "=f"(y) : "f"(x)); return y;
}

// Gate on local wire w in {1..4}: pack-index stride S = 1<<(4-w). Element-wise packed.
template <int S>
__device__ __forceinline__ void gate_local(ull* RE, ull* IM,
                                           float2 G00, float2 G01, float2 G10, float2 G11) {
    ull x00 = sp2(G00.x), ny00 = sp2(-G00.y), y00 = sp2(G00.y);
    ull x01 = sp2(G01.x), ny01 = sp2(-G01.y), y01 = sp2(G01.y);
    ull x10 = sp2(G10.x), ny10 = sp2(-G10.y), y10 = sp2(G10.y);
    ull x11 = sp2(G11.x), ny11 = sp2(-G11.y), y11 = sp2(G11.y);
#pragma unroll
    for (int t = 0; t < 8; t++) {
        int K0 = ((t & ~(S - 1)) << 1) | (t & (S - 1));
        int K1 = K0 + S;
        ull r0 = RE[K0], i0 = IM[K0], r1 = RE[K1], i1 = IM[K1];
        RE[K0] = fma2(x00, r0, fma2(ny00, i0, fma2(x01, r1, mul2(ny01, i1))));
        IM[K0] = fma2(x00, i0, fma2(y00, r0, fma2(x01, i1, mul2(y01, r1))));
        RE[K1] = fma2(x10, r0, fma2(ny10, i0, fma2(x11, r1, mul2(ny11, i1))));
        IM[K1] = fma2(x10, i0, fma2(y10, r0, fma2(x11, i1, mul2(y11, r1))));
    }
}

// Gate on wire 5 (the two lanes inside each pack), swap-form:
// out = P .* st + Q .* laneswap(st), P=(G00,G11), Q=(G01,G10).
__device__ __forceinline__ void gate_w5(ull* RE, ull* IM,
                                        float2 G00, float2 G01, float2 G10, float2 G11) {
    ull Px = pk(G00.x, G11.x), Py = pk(G00.y, G11.y), nPy = pk(-G00.y, -G11.y);
    ull Qx = pk(G01.x, G10.x), Qy = pk(G01.y, G10.y), nQy = pk(-G01.y, -G10.y);
#pragma unroll
    for (int K = 0; K < 16; K++) {
        ull r = RE[K], i = IM[K];
        ull rs = lsw(r), is = lsw(i);
        RE[K] = fma2(Px, r, fma2(nPy, i, fma2(Qx, rs, mul2(nQy, is))));
        IM[K] = fma2(Px, i, fma2(Py, r, fma2(Qx, is, mul2(Qy, rs))));
    }
}

// Gate on wire 0 fused with a PENDING cnot(5,0) from the preceding ring.
// The cnot(5,0) lane merge is absorbed into asymmetric coefficient packs:
//   out = pk(Gd,Go) .* mine + pk(Go,Gd) .* partner     (no lane merges needed)
__device__ __forceinline__ void gate_w0_fused(ull* RE, ull* IM, float2 Gd, float2 Go) {
    ull dx = pk(Gd.x, Go.x), ox = pk(Go.x, Gd.x);
    ull dy = pk(Gd.y, Go.y), oy = pk(Go.y, Gd.y);
    ull ndy = pk(-Gd.y, -Go.y), noy = pk(-Go.y, -Gd.y);
#pragma unroll
    for (int K = 0; K < 16; K++) {
        ull pr = __shfl_xor_sync(0xffffffffu, RE[K], 1);
        ull pi = __shfl_xor_sync(0xffffffffu, IM[K], 1);
        ull r = RE[K], i = IM[K];
        RE[K] = fma2(dx, r, fma2(ndy, i, fma2(ox, pr, mul2(noy, pi))));
        IM[K] = fma2(dx, i, fma2(dy, r, fma2(ox, pi, mul2(oy, pr))));
    }
}

__device__ __forceinline__ void swp(ull& a, ull& b) { ull t = a; a = b; b = t; }

// CNOT ring WITHOUT cnot(0,1) (folded into the wire-1 gate as a row swap) and
// WITHOUT the final cnot(5,0) (fused into the next wire-0 gate / readout):
// applies (1,2)(2,3)(3,4)(4,5) only.
__device__ __forceinline__ void cnot_ring_rest(ull* RE, ull* IM) {
    // cnot(1,2): bit3==1 -> flip bit2  (free renames)
    swp(RE[8], RE[12]); swp(IM[8], IM[12]);
    swp(RE[9], RE[13]); swp(IM[9], IM[13]);
    swp(RE[10], RE[14]); swp(IM[10], IM[14]);
    swp(RE[11], RE[15]); swp(IM[11], IM[15]);
    // cnot(2,3): bit2==1 -> flip bit1
    swp(RE[4], RE[6]);  swp(IM[4], IM[6]);
    swp(RE[5], RE[7]);  swp(IM[5], IM[7]);
    swp(RE[12], RE[14]); swp(IM[12], IM[14]);
    swp(RE[13], RE[15]); swp(IM[13], IM[15]);
    // cnot(3,4): bit1==1 -> flip bit0
    swp(RE[2], RE[3]);  swp(IM[2], IM[3]);
    swp(RE[6], RE[7]);  swp(IM[6], IM[7]);
    swp(RE[10], RE[11]); swp(IM[10], IM[11]);
    swp(RE[14], RE[15]); swp(IM[14], IM[15]);
    // cnot(4,5): bit0==1 -> swap the two lanes of the pack
#pragma unroll
    for (int K = 1; K < 16; K += 2) {
        RE[K] = lsw(RE[K]);
        IM[K] = lsw(IM[K]);
    }
}

__device__ __forceinline__ void makeG(const float2* m, float c, float s,
                                      float2& G00, float2& G01, float2& G10, float2& G11) {
    float2 m00 = m[0], m01 = m[1], m10 = m[2], m11 = m[3];
    G00.x = fmaf(c, m00.x, s * m01.x);  G00.y = fmaf(c, m00.y, s * m01.y);
    G01.x = fmaf(-s, m00.x, c * m01.x); G01.y = fmaf(-s, m00.y, c * m01.y);
    G10.x = fmaf(c, m10.x, s * m11.x);  G10.y = fmaf(c, m10.y, s * m11.y);
    G11.x = fmaf(-s, m10.x, c * m11.x); G11.y = fmaf(-s, m10.y, c * m11.y);
}

__global__ __launch_bounds__(128, 4)
void qsim_kernel(const float* __restrict__ x, float* __restrict__ out, int B) {
    __shared__ float2 sM[NL * NQ * 4];
    if (threadIdx.x < NL * NQ * 4) sM[threadIdx.x] = g_M[threadIdx.x];
    __syncthreads();

    int tid = blockIdx.x * blockDim.x + threadIdx.x;
    int b = tid >> 1;
    if (b >= B) return;
    int p = tid & 1;  // this thread's wire-0 (MSB) value

    // Vectorized x load (x + 6*b is 8B-aligned), then angles.
    float cs[NQ], sn[NQ];
    {
        const float2* xx = reinterpret_cast<const float2*>(x + (size_t)b * NQ);
        float2 x01 = xx[0], x23 = xx[1], x45 = xx[2];
        float xv[NQ] = {x01.x, x01.y, x23.x, x23.y, x45.x, x45.y};
#pragma unroll
        for (int q = 0; q < NQ; q++) {
            float t = 1.5707963267948966f * tanh_fast(xv[q]);
            __sincosf(t, &sn[q], &cs[q]);
        }
    }

    // 32 local amps packed: RE[K] = (re_{2K}, re_{2K+1}), pack lane = wire5.
    // Pack-index bits 3..0 = wires 1..4.
    ull RE[16], IM[16];

    // ---- Layer 0: product state |0..0> -> tensor of first gate columns.
    //      Ring0's cnot(0,1) is folded into the wire-1 factor (v0<->v1 for p=1). ----
    {
        float2 a;  // wire-0 factor for this thread
        {
            float2 ma = p ? sM[2] : sM[0];
            float2 mb = p ? sM[3] : sM[1];
            a.x = fmaf(cs[0], ma.x, sn[0] * mb.x);
            a.y = fmaf(cs[0], ma.y, sn[0] * mb.y);
        }
        {
            float2 m00 = sM[5 * 4 + 0], m01 = sM[5 * 4 + 1];
            float2 m10 = sM[5 * 4 + 2], m11 = sM[5 * 4 + 3];
            float2 v0 = make_float2(fmaf(cs[5], m00.x, sn[5] * m01.x),
                                    fmaf(cs[5], m00.y, sn[5] * m01.y));
            float2 v1 = make_float2(fmaf(cs[5], m10.x, sn[5] * m11.x),
                                    fmaf(cs[5], m10.y, sn[5] * m11.y));
            ull V5X = pk(v0.x, v1.x), V5Y = pk(v0.y, v1.y), V5Yn = pk(-v0.y, -v1.y);
            RE[0] = fma2(sp2(a.x), V5X, mul2(sp2(a.y), V5Yn));
            IM[0] = fma2(sp2(a.x), V5Y, mul2(sp2(a.y), V5X));
        }
#pragma unroll
        for (int q = 1; q <= 4; q++) {
            float2 m00 = sM[q * 4 + 0], m01 = sM[q * 4 + 1];
            float2 m10 = sM[q * 4 + 2], m11 = sM[q * 4 + 3];
            float2 v0 = make_float2(fmaf(cs[q], m00.x, sn[q] * m01.x),
                                    fmaf(cs[q], m00.y, sn[q] * m01.y));
            float2 v1 = make_float2(fmaf(cs[q], m10.x, sn[q] * m11.x),
                                    fmaf(cs[q], m10.y, sn[q] * m11.y));
            if (q == 1) {
                // fold ring0's cnot(0,1): p==1 threads see wire1 flipped afterwards,
                // equivalent to swapping the wire-1 factor components.
                float2 t0 = v0, t1 = v1;
                v0 = p ? t1 : t0;
                v1 = p ? t0 : t1;
            }
            ull x0 = sp2(v0.x), ny0 = sp2(-v0.y), y0 = sp2(v0.y);
            ull x1 = sp2(v1.x), ny1 = sp2(-v1.y), y1 = sp2(v1.y);
            int n = 1 << (q - 1);
#pragma unroll
            for (int k = 15; k >= 0; k--) {
                if (k < n) {
                    ull r = RE[k], i = IM[k];
                    RE[2 * k + 1] = fma2(x1, r, mul2(ny1, i));
                    IM[2 * k + 1] = fma2(x1, i, mul2(y1, r));
                    RE[2 * k]     = fma2(x0, r, mul2(ny0, i));
                    IM[2 * k]     = fma2(x0, i, mul2(y0, r));
                }
            }
        }
    }
    cnot_ring_rest(RE, IM);  // (1,2)(2,3)(3,4)(4,5); cnot(5,0) pending

    // ---- Layers 1..2 ----
    // Order within a layer (all 1q gates commute): w0 first (resolves pending
    // cnot(5,0)), then w2,w3,w4,w5, then w1 LAST with cnot(0,1) folded in as a
    // row swap (X^p · G), then the rest of the ring.
#pragma unroll
    for (int layer = 1; layer < NL; layer++) {
        const float2* mbase = &sM[layer * NQ * 4];
        float2 G00, G01, G10, G11;
        // wire 0 (cross-thread), fused with pending cnot(5,0).
        {
            float2 ma = p ? mbase[2] : mbase[0];
            float2 mb = p ? mbase[3] : mbase[1];
            float c = cs[0], s = sn[0];
            float2 u = make_float2(fmaf(c, ma.x, s * mb.x), fmaf(c, ma.y, s * mb.y));
            float2 v = make_float2(fmaf(-s, ma.x, c * mb.x), fmaf(-s, ma.y, c * mb.y));
            float2 Gd = p ? v : u;
            float2 Go = p ? u : v;
            gate_w0_fused(RE, IM, Gd, Go);
        }
        // wires 2..4 (local packed)
        makeG(mbase + 8, cs[2], sn[2], G00, G01, G10, G11);
        gate_local<4>(RE, IM, G00, G01, G10, G11);
        makeG(mbase + 12, cs[3], sn[3], G00, G01, G10, G11);
        gate_local<2>(RE, IM, G00, G01, G10, G11);
        makeG(mbase + 16, cs[4], sn[4], G00, G01, G10, G11);
        gate_local<1>(RE, IM, G00, G01, G10, G11);
        // wire 5 (intra-pack, swap-form)
        makeG(mbase + 20, cs[5], sn[5], G00, G01, G10, G11);
        gate_w5(RE, IM, G00, G01, G10, G11);
        // wire 1 LAST, with cnot(0,1) folded: p==1 threads apply X·G (row swap).
        makeG(mbase + 4, cs[1], sn[1], G00, G01, G10, G11);
        {
            float2 H00 = p ? G10 : G00, H01 = p ? G11 : G01;
            float2 H10 = p ? G00 : G10, H11 = p ? G01 : G11;
            gate_local<8>(RE, IM, H00, H01, H10, H11);
        }

        cnot_ring_rest(RE, IM);  // cnot(5,0) pending again
    }

    // ---- Readout: Walsh butterfly over pack index (signs = wire bits),
    //      final cnot(5,0) folded into the e0 sign. All values stay packed. ----
    ull PR[16];
#pragma unroll
    for (int K = 0; K < 16; K++) {
        PR[K] = fma2(RE[K], RE[K], mul2(IM[K], IM[K]));
    }
    // level A: bit0 of K = wire4
    ull sA[8], dA[8];
#pragma unroll
    for (int k = 0; k < 8; k++) {
        sA[k] = add2(PR[2 * k], PR[2 * k + 1]);
        dA[k] = add2(PR[2 * k], neg2(PR[2 * k + 1]));
    }
    ull E4 = add2(add2(add2(dA[0], dA[1]), add2(dA[2], dA[3])),
                  add2(add2(dA[4], dA[5]), add2(dA[6], dA[7])));
    // level B: bit1 = wire3
    ull sB[4], dB[4];
#pragma unroll
    for (int k = 0; k < 4; k++) {
        sB[k] = add2(sA[2 * k], sA[2 * k + 1]);
        dB[k] = add2(sA[2 * k], neg2(sA[2 * k + 1]));
    }
    ull E3 = add2(add2(dB[0], dB[1]), add2(dB[2], dB[3]));
    // level C: bit2 = wire2
    ull sC0 = add2(sB[0], sB[1]), sC1 = add2(sB[2], sB[3]);
    ull E2 = add2(add2(sB[0], neg2(sB[1])), add2(sB[2], neg2(sB[3])));
    // level D: bit3 = wire1
    ull At = add2(sC0, sC1);
    ull E1 = add2(sC0, neg2(sC1));

    float dsum = flo(At) - fhi(At);
    float e0 = p ? -dsum : dsum;  // lo lane: wire0 = p; hi lane: wire0 = 1-p
    float e5 = dsum;              // wire5 = lane, unaffected by cnot(5,0)
    float e1 = flo(E1) + fhi(E1);
    float e2 = flo(E2) + fhi(E2);
    float e3 = flo(E3) + fhi(E3);
    float e4 = flo(E4) + fhi(E4);
    e0 += __shfl_xor_sync(0xffffffffu, e0, 1);
    e1 += __shfl_xor_sync(0xffffffffu, e1, 1);
    e2 += __shfl_xor_sync(0xffffffffu, e2, 1);
    e3 += __shfl_xor_sync(0xffffffffu, e3, 1);
    e4 += __shfl_xor_sync(0xffffffffu, e4, 1);
    e5 += __shfl_xor_sync(0xffffffffu, e5, 1);

    // Vectorized stores: b*6 floats = 24B base (8B-aligned).
    float* ob = out + (size_t)b * NQ;
    if (p == 0) {
        *reinterpret_cast<float2*>(ob) = make_float2(e0, e1);  // ob[0..1]
        ob[2] = e2;
    } else {
        ob[3] = e3;
        *reinterpret_cast<float2*>(ob + 4) = make_float2(e4, e5);  // ob[4..5]
    }
}

extern "C" void kernel_launch(void* const* d_in, const int* in_sizes, int n_in,
                              void* d_out, int out_size) {
    const float* x = (const float*)d_in[0];
    const float* w = (const float*)d_in[1];
    float* out = (float*)d_out;
    int B = in_sizes[0] / NQ;

    setup_gates<<<1, 32>>>(w);

    const int threads = 128;
    long long total = 2LL * B;
    int blocks = (int)((total + threads - 1) / threads);
    qsim_kernel<<<blocks, threads>>>(x, out, B);
}

// round 11
// speedup vs baseline: 1.1871x; 1.0643x over previous
#include <cuda_runtime.h>

#define NQ 6
#define NL 3

typedef unsigned long long ull;

// ---- packed f32x2 helpers ----
__device__ __forceinline__ ull fma2(ull a, ull b, ull c) {
    ull d; asm("fma.rn.f32x2 %0,%1,%2,%3;" : "=l"(d) : "l"(a), "l"(b), "l"(c)); return d;
}
__device__ __forceinline__ ull mul2(ull a, ull b) {
    ull d; asm("mul.rn.f32x2 %0,%1,%2;" : "=l"(d) : "l"(a), "l"(b)); return d;
}
__device__ __forceinline__ ull add2(ull a, ull b) {
    ull d; asm("add.rn.f32x2 %0,%1,%2;" : "=l"(d) : "l"(a), "l"(b)); return d;
}
__device__ __forceinline__ ull pk(float lo, float hi) {
    ull d; asm("mov.b64 %0,{%1,%2};" : "=l"(d) : "f"(lo), "f"(hi)); return d;
}
__device__ __forceinline__ ull sp2(float x) { return pk(x, x); }
__device__ __forceinline__ float flo(ull v) { return __uint_as_float((unsigned)v); }
__device__ __forceinline__ float fhi(ull v) { return __uint_as_float((unsigned)(v >> 32)); }
__device__ __forceinline__ ull lsw(ull v) { return pk(fhi(v), flo(v)); }     // lane swap
__device__ __forceinline__ ull neg2(ull v) { return v ^ 0x8000000080000000ULL; }
__device__ __forceinline__ float tanh_fast(float x) {
    float y; asm("tanh.approx.f32 %0, %1;" : "=f"(y) : "f"(x)); return y;
}

// Gate on local wire w in {1..4}: pack-index stride S = 1<<(4-w). Element-wise packed.
template <int S>
__device__ __forceinline__ void gate_local(ull* RE, ull* IM,
                                           float2 G00, float2 G01, float2 G10, float2 G11) {
    ull x00 = sp2(G00.x), ny00 = sp2(-G00.y), y00 = sp2(G00.y);
    ull x01 = sp2(G01.x), ny01 = sp2(-G01.y), y01 = sp2(G01.y);
    ull x10 = sp2(G10.x), ny10 = sp2(-G10.y), y10 = sp2(G10.y);
    ull x11 = sp2(G11.x), ny11 = sp2(-G11.y), y11 = sp2(G11.y);
#pragma unroll
    for (int t = 0; t < 8; t++) {
        int K0 = ((t & ~(S - 1)) << 1) | (t & (S - 1));
        int K1 = K0 + S;
        ull r0 = RE[K0], i0 = IM[K0], r1 = RE[K1], i1 = IM[K1];
        RE[K0] = fma2(x00, r0, fma2(ny00, i0, fma2(x01, r1, mul2(ny01, i1))));
        IM[K0] = fma2(x00, i0, fma2(y00, r0, fma2(x01, i1, mul2(y01, r1))));
        RE[K1] = fma2(x10, r0, fma2(ny10, i0, fma2(x11, r1, mul2(ny11, i1))));
        IM[K1] = fma2(x10, i0, fma2(y10, r0, fma2(x11, i1, mul2(y11, r1))));
    }
}

// Gate on wire 5 (the two lanes inside each pack), swap-form:
// out = P .* st + Q .* laneswap(st), P=(G00,G11), Q=(G01,G10).
__device__ __forceinline__ void gate_w5(ull* RE, ull* IM,
                                        float2 G00, float2 G01, float2 G10, float2 G11) {
    ull Px = pk(G00.x, G11.x), Py = pk(G00.y, G11.y), nPy = pk(-G00.y, -G11.y);
    ull Qx = pk(G01.x, G10.x), Qy = pk(G01.y, G10.y), nQy = pk(-G01.y, -G10.y);
#pragma unroll
    for (int K = 0; K < 16; K++) {
        ull r = RE[K], i = IM[K];
        ull rs = lsw(r), is = lsw(i);
        RE[K] = fma2(Px, r, fma2(nPy, i, fma2(Qx, rs, mul2(nQy, is))));
        IM[K] = fma2(Px, i, fma2(Py, r, fma2(Qx, is, mul2(Qy, rs))));
    }
}

// Gate on wire 0 fused with a PENDING cnot(5,0) from the preceding ring.
// The cnot(5,0) lane merge is absorbed into asymmetric coefficient packs:
//   out = pk(Gd,Go) .* mine + pk(Go,Gd) .* partner     (no lane merges needed)
// 2-deep software pipeline: partner shuffles for K+1 are issued while the
// 16 fma ops of iteration K execute, hiding the ~26cy SHFL latency.
__device__ __forceinline__ void gate_w0_fused(ull* RE, ull* IM, float2 Gd, float2 Go) {
    ull dx = pk(Gd.x, Go.x), ox = pk(Go.x, Gd.x);
    ull dy = pk(Gd.y, Go.y), oy = pk(Go.y, Gd.y);
    ull ndy = pk(-Gd.y, -Go.y), noy = pk(-Go.y, -Gd.y);
    ull pr = __shfl_xor_sync(0xffffffffu, RE[0], 1);
    ull pi = __shfl_xor_sync(0xffffffffu, IM[0], 1);
#pragma unroll
    for (int K = 0; K < 16; K++) {
        ull prn = 0, pin = 0;
        if (K < 15) {
            prn = __shfl_xor_sync(0xffffffffu, RE[K + 1], 1);
            pin = __shfl_xor_sync(0xffffffffu, IM[K + 1], 1);
        }
        ull r = RE[K], i = IM[K];
        RE[K] = fma2(dx, r, fma2(ndy, i, fma2(ox, pr, mul2(noy, pi))));
        IM[K] = fma2(dx, i, fma2(dy, r, fma2(ox, pi, mul2(oy, pr))));
        pr = prn; pi = pin;
    }
}

__device__ __forceinline__ void swp(ull& a, ull& b) { ull t = a; a = b; b = t; }

// CNOT ring WITHOUT cnot(0,1) (folded into the wire-1 gate as a row swap) and
// WITHOUT the final cnot(5,0) (fused into the next wire-0 gate / readout):
// applies (1,2)(2,3)(3,4)(4,5) only.
__device__ __forceinline__ void cnot_ring_rest(ull* RE, ull* IM) {
    // cnot(1,2): bit3==1 -> flip bit2  (free renames)
    swp(RE[8], RE[12]); swp(IM[8], IM[12]);
    swp(RE[9], RE[13]); swp(IM[9], IM[13]);
    swp(RE[10], RE[14]); swp(IM[10], IM[14]);
    swp(RE[11], RE[15]); swp(IM[11], IM[15]);
    // cnot(2,3): bit2==1 -> flip bit1
    swp(RE[4], RE[6]);  swp(IM[4], IM[6]);
    swp(RE[5], RE[7]);  swp(IM[5], IM[7]);
    swp(RE[12], RE[14]); swp(IM[12], IM[14]);
    swp(RE[13], RE[15]); swp(IM[13], IM[15]);
    // cnot(3,4): bit1==1 -> flip bit0
    swp(RE[2], RE[3]);  swp(IM[2], IM[3]);
    swp(RE[6], RE[7]);  swp(IM[6], IM[7]);
    swp(RE[10], RE[11]); swp(IM[10], IM[11]);
    swp(RE[14], RE[15]); swp(IM[14], IM[15]);
    // cnot(4,5): bit0==1 -> swap the two lanes of the pack
#pragma unroll
    for (int K = 1; K < 16; K += 2) {
        RE[K] = lsw(RE[K]);
        IM[K] = lsw(IM[K]);
    }
}

__device__ __forceinline__ void makeG(const float2* m, float c, float s,
                                      float2& G00, float2& G01, float2& G10, float2& G11) {
    float2 m00 = m[0], m01 = m[1], m10 = m[2], m11 = m[3];
    G00.x = fmaf(c, m00.x, s * m01.x);  G00.y = fmaf(c, m00.y, s * m01.y);
    G01.x = fmaf(-s, m00.x, c * m01.x); G01.y = fmaf(-s, m00.y, c * m01.y);
    G10.x = fmaf(c, m10.x, s * m11.x);  G10.y = fmaf(c, m10.y, s * m11.y);
    G11.x = fmaf(-s, m10.x, c * m11.x); G11.y = fmaf(-s, m10.y, c * m11.y);
}

__global__ __launch_bounds__(128, 4)
void qsim_kernel(const float* __restrict__ x, const float* __restrict__ w,
                 float* __restrict__ out, int B) {
    // In-block gate setup (no separate launch, no global round-trip):
    // threads 0..17 each build one gate's M = RZ(w2)@RY(w1)@RZ(w0).
    __shared__ float2 sM[NL * NQ * 4];
    {
        int g = threadIdx.x;
        if (g < NL * NQ) {
            float w0 = w[g * 3 + 0];
            float w1 = w[g * 3 + 1];
            float w2 = w[g * 3 + 2];
            float s1, c1, sp_, cp_, sm2, cm2;
            sincosf(0.5f * w1, &s1, &c1);
            sincosf(0.5f * (w0 + w2), &sp_, &cp_);
            sincosf(0.5f * (w0 - w2), &sm2, &cm2);
            sM[g * 4 + 0] = make_float2(c1 * cp_, -c1 * sp_);   // M00
            sM[g * 4 + 1] = make_float2(-s1 * cm2, -s1 * sm2);  // M01
            sM[g * 4 + 2] = make_float2(s1 * cm2, -s1 * sm2);   // M10
            sM[g * 4 + 3] = make_float2(c1 * cp_, c1 * sp_);    // M11
        }
    }
    __syncthreads();

    int tid = blockIdx.x * blockDim.x + threadIdx.x;
    int b = tid >> 1;
    if (b >= B) return;
    int p = tid & 1;  // this thread's wire-0 (MSB) value

    // Vectorized x load (x + 6*b is 8B-aligned), then angles.
    float cs[NQ], sn[NQ];
    {
        const float2* xx = reinterpret_cast<const float2*>(x + (size_t)b * NQ);
        float2 x01 = xx[0], x23 = xx[1], x45 = xx[2];
        float xv[NQ] = {x01.x, x01.y, x23.x, x23.y, x45.x, x45.y};
#pragma unroll
        for (int q = 0; q < NQ; q++) {
            float t = 1.5707963267948966f * tanh_fast(xv[q]);
            __sincosf(t, &sn[q], &cs[q]);
        }
    }

    // 32 local amps packed: RE[K] = (re_{2K}, re_{2K+1}), pack lane = wire5.
    // Pack-index bits 3..0 = wires 1..4.
    ull RE[16], IM[16];

    // ---- Layer 0: product state |0..0> -> tensor of first gate columns.
    //      Ring0's cnot(0,1) is folded into the wire-1 factor (v0<->v1 for p=1). ----
    {
        float2 a;  // wire-0 factor for this thread
        {
            float2 ma = p ? sM[2] : sM[0];
            float2 mb = p ? sM[3] : sM[1];
            a.x = fmaf(cs[0], ma.x, sn[0] * mb.x);
            a.y = fmaf(cs[0], ma.y, sn[0] * mb.y);
        }
        {
            float2 m00 = sM[5 * 4 + 0], m01 = sM[5 * 4 + 1];
            float2 m10 = sM[5 * 4 + 2], m11 = sM[5 * 4 + 3];
            float2 v0 = make_float2(fmaf(cs[5], m00.x, sn[5] * m01.x),
                                    fmaf(cs[5], m00.y, sn[5] * m01.y));
            float2 v1 = make_float2(fmaf(cs[5], m10.x, sn[5] * m11.x),
                                    fmaf(cs[5], m10.y, sn[5] * m11.y));
            ull V5X = pk(v0.x, v1.x), V5Y = pk(v0.y, v1.y), V5Yn = pk(-v0.y, -v1.y);
            RE[0] = fma2(sp2(a.x), V5X, mul2(sp2(a.y), V5Yn));
            IM[0] = fma2(sp2(a.x), V5Y, mul2(sp2(a.y), V5X));
        }
#pragma unroll
        for (int q = 1; q <= 4; q++) {
            float2 m00 = sM[q * 4 + 0], m01 = sM[q * 4 + 1];
            float2 m10 = sM[q * 4 + 2], m11 = sM[q * 4 + 3];
            float2 v0 = make_float2(fmaf(cs[q], m00.x, sn[q] * m01.x),
                                    fmaf(cs[q], m00.y, sn[q] * m01.y));
            float2 v1 = make_float2(fmaf(cs[q], m10.x, sn[q] * m11.x),
                                    fmaf(cs[q], m10.y, sn[q] * m11.y));
            if (q == 1) {
                // fold ring0's cnot(0,1): p==1 threads see wire1 flipped afterwards,
                // equivalent to swapping the wire-1 factor components.
                float2 t0 = v0, t1 = v1;
                v0 = p ? t1 : t0;
                v1 = p ? t0 : t1;
            }
            ull x0 = sp2(v0.x), ny0 = sp2(-v0.y), y0 = sp2(v0.y);
            ull x1 = sp2(v1.x), ny1 = sp2(-v1.y), y1 = sp2(v1.y);
            int n = 1 << (q - 1);
#pragma unroll
            for (int k = 15; k >= 0; k--) {
                if (k < n) {
                    ull r = RE[k], i = IM[k];
                    RE[2 * k + 1] = fma2(x1, r, mul2(ny1, i));
                    IM[2 * k + 1] = fma2(x1, i, mul2(y1, r));
                    RE[2 * k]     = fma2(x0, r, mul2(ny0, i));
                    IM[2 * k]     = fma2(x0, i, mul2(y0, r));
                }
            }
        }
    }
    cnot_ring_rest(RE, IM);  // (1,2)(2,3)(3,4)(4,5); cnot(5,0) pending

    // ---- Layers 1..2 ----
    // Order within a layer (all 1q gates commute): w0 first (resolves pending
    // cnot(5,0)), then w2,w3,w4,w5, then w1 LAST with cnot(0,1) folded in as a
    // row swap (X^p · G), then the rest of the ring.
#pragma unroll
    for (int layer = 1; layer < NL; layer++) {
        const float2* mbase = &sM[layer * NQ * 4];
        float2 G00, G01, G10, G11;
        // wire 0 (cross-thread), fused with pending cnot(5,0).
        {
            float2 ma = p ? mbase[2] : mbase[0];
            float2 mb = p ? mbase[3] : mbase[1];
            float c = cs[0], s = sn[0];
            float2 u = make_float2(fmaf(c, ma.x, s * mb.x), fmaf(c, ma.y, s * mb.y));
            float2 v = make_float2(fmaf(-s, ma.x, c * mb.x), fmaf(-s, ma.y, c * mb.y));
            float2 Gd = p ? v : u;
            float2 Go = p ? u : v;
            gate_w0_fused(RE, IM, Gd, Go);
        }
        // wires 2..4 (local packed)
        makeG(mbase + 8, cs[2], sn[2], G00, G01, G10, G11);
        gate_local<4>(RE, IM, G00, G01, G10, G11);
        makeG(mbase + 12, cs[3], sn[3], G00, G01, G10, G11);
        gate_local<2>(RE, IM, G00, G01, G10, G11);
        makeG(mbase + 16, cs[4], sn[4], G00, G01, G10, G11);
        gate_local<1>(RE, IM, G00, G01, G10, G11);
        // wire 5 (intra-pack, swap-form)
        makeG(mbase + 20, cs[5], sn[5], G00, G01, G10, G11);
        gate_w5(RE, IM, G00, G01, G10, G11);
        // wire 1 LAST, with cnot(0,1) folded: p==1 threads apply X·G (row swap).
        makeG(mbase + 4, cs[1], sn[1], G00, G01, G10, G11);
        {
            float2 H00 = p ? G10 : G00, H01 = p ? G11 : G01;
            float2 H10 = p ? G00 : G10, H11 = p ? G01 : G11;
            gate_local<8>(RE, IM, H00, H01, H10, H11);
        }

        cnot_ring_rest(RE, IM);  // cnot(5,0) pending again
    }

    // ---- Readout: Walsh butterfly over pack index (signs = wire bits),
    //      final cnot(5,0) folded into the e0 sign. All values stay packed. ----
    ull PR[16];
#pragma unroll
    for (int K = 0; K < 16; K++) {
        PR[K] = fma2(RE[K], RE[K], mul2(IM[K], IM[K]));
    }
    // level A: bit0 of K = wire4
    ull sA[8], dA[8];
#pragma unroll
    for (int k = 0; k < 8; k++) {
        sA[k] = add2(PR[2 * k], PR[2 * k + 1]);
        dA[k] = add2(PR[2 * k], neg2(PR[2 * k + 1]));
    }
    ull E4 = add2(add2(add2(dA[0], dA[1]), add2(dA[2], dA[3])),
                  add2(add2(dA[4], dA[5]), add2(dA[6], dA[7])));
    // level B: bit1 = wire3
    ull sB[4], dB[4];
#pragma unroll
    for (int k = 0; k < 4; k++) {
        sB[k] = add2(sA[2 * k], sA[2 * k + 1]);
        dB[k] = add2(sA[2 * k], neg2(sA[2 * k + 1]));
    }
    ull E3 = add2(add2(dB[0], dB[1]), add2(dB[2], dB[3]));
    // level C: bit2 = wire2
    ull sC0 = add2(sB[0], sB[1]), sC1 = add2(sB[2], sB[3]);
    ull E2 = add2(add2(sB[0], neg2(sB[1])), add2(sB[2], neg2(sB[3])));
    // level D: bit3 = wire1
    ull At = add2(sC0, sC1);
    ull E1 = add2(sC0, neg2(sC1));

    float dsum = flo(At) - fhi(At);
    float e0 = p ? -dsum : dsum;  // lo lane: wire0 = p; hi lane: wire0 = 1-p
    float e5 = dsum;              // wire5 = lane, unaffected by cnot(5,0)
    float e1 = flo(E1) + fhi(E1);
    float e2 = flo(E2) + fhi(E2);
    float e3 = flo(E3) + fhi(E3);
    float e4 = flo(E4) + fhi(E4);
    e0 += __shfl_xor_sync(0xffffffffu, e0, 1);
    e1 += __shfl_xor_sync(0xffffffffu, e1, 1);
    e2 += __shfl_xor_sync(0xffffffffu, e2, 1);
    e3 += __shfl_xor_sync(0xffffffffu, e3, 1);
    e4 += __shfl_xor_sync(0xffffffffu, e4, 1);
    e5 += __shfl_xor_sync(0xffffffffu, e5, 1);

    // Vectorized stores: b*6 floats = 24B base (8B-aligned).
    float* ob = out + (size_t)b * NQ;
    if (p == 0) {
        *reinterpret_cast<float2*>(ob) = make_float2(e0, e1);  // ob[0..1]
        ob[2] = e2;
    } else {
        ob[3] = e3;
        *reinterpret_cast<float2*>(ob + 4) = make_float2(e4, e5);  // ob[4..5]
    }
}

extern "C" void kernel_launch(void* const* d_in, const int* in_sizes, int n_in,
                              void* d_out, int out_size) {
    const float* x = (const float*)d_in[0];
    const float* w = (const float*)d_in[1];
    float* out = (float*)d_out;
    int B = in_sizes[0] / NQ;

    const int threads = 128;
    long long total = 2LL * B;
    int blocks = (int)((total + threads - 1) / threads);
    qsim_kernel<<<blocks, threads>>>(x, w, out, B);
}

// round 12
// speedup vs baseline: 1.2131x; 1.0219x over previous
#include <cuda_runtime.h>

#define NQ 6
#define NL 3

typedef unsigned long long ull;

// ---- packed f32x2 helpers ----
__device__ __forceinline__ ull fma2(ull a, ull b, ull c) {
    ull d; asm("fma.rn.f32x2 %0,%1,%2,%3;" : "=l"(d) : "l"(a), "l"(b), "l"(c)); return d;
}
__device__ __forceinline__ ull mul2(ull a, ull b) {
    ull d; asm("mul.rn.f32x2 %0,%1,%2;" : "=l"(d) : "l"(a), "l"(b)); return d;
}
__device__ __forceinline__ ull add2(ull a, ull b) {
    ull d; asm("add.rn.f32x2 %0,%1,%2;" : "=l"(d) : "l"(a), "l"(b)); return d;
}
__device__ __forceinline__ ull pk(float lo, float hi) {
    ull d; asm("mov.b64 %0,{%1,%2};" : "=l"(d) : "f"(lo), "f"(hi)); return d;
}
__device__ __forceinline__ ull sp2(float x) { return pk(x, x); }
__device__ __forceinline__ float flo(ull v) { return __uint_as_float((unsigned)v); }
__device__ __forceinline__ float fhi(ull v) { return __uint_as_float((unsigned)(v >> 32)); }
__device__ __forceinline__ ull lsw(ull v) { return pk(fhi(v), flo(v)); }     // lane swap
__device__ __forceinline__ float tanh_fast(float x) {
    float y; asm("tanh.approx.f32 %0, %1;" : "=f"(y) : "f"(x)); return y;
}
// a - b on the fma pipe (1 op; avoids add2 + 64-bit sign-flip LOPs)
__device__ __forceinline__ ull sub2f(ull a, ull b, ull MONE) { return fma2(MONE, b, a); }

// Gate on local wire w in {1..4}: pack-index stride S = 1<<(4-w). Element-wise packed.
template <int S>
__device__ __forceinline__ void gate_local(ull* RE, ull* IM,
                                           float2 G00, float2 G01, float2 G10, float2 G11) {
    ull x00 = sp2(G00.x), ny00 = sp2(-G00.y), y00 = sp2(G00.y);
    ull x01 = sp2(G01.x), ny01 = sp2(-G01.y), y01 = sp2(G01.y);
    ull x10 = sp2(G10.x), ny10 = sp2(-G10.y), y10 = sp2(G10.y);
    ull x11 = sp2(G11.x), ny11 = sp2(-G11.y), y11 = sp2(G11.y);
#pragma unroll
    for (int t = 0; t < 8; t++) {
        int K0 = ((t & ~(S - 1)) << 1) | (t & (S - 1));
        int K1 = K0 + S;
        ull r0 = RE[K0], i0 = IM[K0], r1 = RE[K1], i1 = IM[K1];
        RE[K0] = fma2(x00, r0, fma2(ny00, i0, fma2(x01, r1, mul2(ny01, i1))));
        IM[K0] = fma2(x00, i0, fma2(y00, r0, fma2(x01, i1, mul2(y01, r1))));
        RE[K1] = fma2(x10, r0, fma2(ny10, i0, fma2(x11, r1, mul2(ny11, i1))));
        IM[K1] = fma2(x10, i0, fma2(y10, r0, fma2(x11, i1, mul2(y11, r1))));
    }
}

// Gate on wire 5 (the two lanes inside each pack), swap-form:
// out = P .* st + Q .* laneswap(st), P=(G00,G11), Q=(G01,G10).
__device__ __forceinline__ void gate_w5(ull* RE, ull* IM,
                                        float2 G00, float2 G01, float2 G10, float2 G11) {
    ull Px = pk(G00.x, G11.x), Py = pk(G00.y, G11.y), nPy = pk(-G00.y, -G11.y);
    ull Qx = pk(G01.x, G10.x), Qy = pk(G01.y, G10.y), nQy = pk(-G01.y, -G10.y);
#pragma unroll
    for (int K = 0; K < 16; K++) {
        ull r = RE[K], i = IM[K];
        ull rs = lsw(r), is = lsw(i);
        RE[K] = fma2(Px, r, fma2(nPy, i, fma2(Qx, rs, mul2(nQy, is))));
        IM[K] = fma2(Px, i, fma2(Py, r, fma2(Qx, is, mul2(Qy, rs))));
    }
}

// Gate on wire 0 fused with a PENDING cnot(5,0) from the preceding ring.
// Asymmetric coefficient packs absorb the lane merge; 2-deep SHFL pipeline.
__device__ __forceinline__ void gate_w0_fused(ull* RE, ull* IM, float2 Gd, float2 Go) {
    ull dx = pk(Gd.x, Go.x), ox = pk(Go.x, Gd.x);
    ull dy = pk(Gd.y, Go.y), oy = pk(Go.y, Gd.y);
    ull ndy = pk(-Gd.y, -Go.y), noy = pk(-Go.y, -Gd.y);
    ull pr = __shfl_xor_sync(0xffffffffu, RE[0], 1);
    ull pi = __shfl_xor_sync(0xffffffffu, IM[0], 1);
#pragma unroll
    for (int K = 0; K < 16; K++) {
        ull prn = 0, pin = 0;
        if (K < 15) {
            prn = __shfl_xor_sync(0xffffffffu, RE[K + 1], 1);
            pin = __shfl_xor_sync(0xffffffffu, IM[K + 1], 1);
        }
        ull r = RE[K], i = IM[K];
        RE[K] = fma2(dx, r, fma2(ndy, i, fma2(ox, pr, mul2(noy, pi))));
        IM[K] = fma2(dx, i, fma2(dy, r, fma2(ox, pi, mul2(oy, pr))));
        pr = prn; pi = pin;
    }
}

__device__ __forceinline__ void swp(ull& a, ull& b) { ull t = a; a = b; b = t; }

// CNOT ring WITHOUT cnot(0,1) (folded into the wire-1 gate as a row swap) and
// WITHOUT the final cnot(5,0) (fused into the next wire-0 gate):
// applies (1,2)(2,3)(3,4)(4,5) only.
__device__ __forceinline__ void cnot_ring_rest(ull* RE, ull* IM) {
    // cnot(1,2): bit3==1 -> flip bit2  (free renames)
    swp(RE[8], RE[12]); swp(IM[8], IM[12]);
    swp(RE[9], RE[13]); swp(IM[9], IM[13]);
    swp(RE[10], RE[14]); swp(IM[10], IM[14]);
    swp(RE[11], RE[15]); swp(IM[11], IM[15]);
    // cnot(2,3): bit2==1 -> flip bit1
    swp(RE[4], RE[6]);  swp(IM[4], IM[6]);
    swp(RE[5], RE[7]);  swp(IM[5], IM[7]);
    swp(RE[12], RE[14]); swp(IM[12], IM[14]);
    swp(RE[13], RE[15]); swp(IM[13], IM[15]);
    // cnot(3,4): bit1==1 -> flip bit0
    swp(RE[2], RE[3]);  swp(IM[2], IM[3]);
    swp(RE[6], RE[7]);  swp(IM[6], IM[7]);
    swp(RE[10], RE[11]); swp(IM[10], IM[11]);
    swp(RE[14], RE[15]); swp(IM[14], IM[15]);
    // cnot(4,5): bit0==1 -> swap the two lanes of the pack
#pragma unroll
    for (int K = 1; K < 16; K += 2) {
        RE[K] = lsw(RE[K]);
        IM[K] = lsw(IM[K]);
    }
}

__device__ __forceinline__ void makeG(const float2* m, float c, float s,
                                      float2& G00, float2& G01, float2& G10, float2& G11) {
    float2 m00 = m[0], m01 = m[1], m10 = m[2], m11 = m[3];
    G00.x = fmaf(c, m00.x, s * m01.x);  G00.y = fmaf(c, m00.y, s * m01.y);
    G01.x = fmaf(-s, m00.x, c * m01.x); G01.y = fmaf(-s, m00.y, c * m01.y);
    G10.x = fmaf(c, m10.x, s * m11.x);  G10.y = fmaf(c, m10.y, s * m11.y);
    G11.x = fmaf(-s, m10.x, c * m11.x); G11.y = fmaf(-s, m10.y, c * m11.y);
}

// One mid-circuit layer's single-qubit gates (w0 consumes pending cnot(5,0);
// w1 applied LAST with this ring's cnot(0,1) folded in as a row swap).
__device__ __forceinline__ void apply_gates(ull* RE, ull* IM, const float2* mbase,
                                            const float* cs, const float* sn, int p,
                                            bool fold_w1) {
    float2 G00, G01, G10, G11;
    // wire 0 (cross-thread), fused with pending cnot(5,0).
    {
        float2 ma = p ? mbase[2] : mbase[0];
        float2 mb = p ? mbase[3] : mbase[1];
        float c = cs[0], s = sn[0];
        float2 u = make_float2(fmaf(c, ma.x, s * mb.x), fmaf(c, ma.y, s * mb.y));
        float2 v = make_float2(fmaf(-s, ma.x, c * mb.x), fmaf(-s, ma.y, c * mb.y));
        float2 Gd = p ? v : u;
        float2 Go = p ? u : v;
        gate_w0_fused(RE, IM, Gd, Go);
    }
    // wires 2..4 (local packed)
    makeG(mbase + 8, cs[2], sn[2], G00, G01, G10, G11);
    gate_local<4>(RE, IM, G00, G01, G10, G11);
    makeG(mbase + 12, cs[3], sn[3], G00, G01, G10, G11);
    gate_local<2>(RE, IM, G00, G01, G10, G11);
    makeG(mbase + 16, cs[4], sn[4], G00, G01, G10, G11);
    gate_local<1>(RE, IM, G00, G01, G10, G11);
    // wire 5 (intra-pack, swap-form)
    makeG(mbase + 20, cs[5], sn[5], G00, G01, G10, G11);
    gate_w5(RE, IM, G00, G01, G10, G11);
    // wire 1 LAST; optional cnot(0,1) fold = X^p row swap.
    makeG(mbase + 4, cs[1], sn[1], G00, G01, G10, G11);
    if (fold_w1) {
        float2 H00 = p ? G10 : G00, H01 = p ? G11 : G01;
        float2 H10 = p ? G00 : G10, H11 = p ? G01 : G11;
        gate_local<8>(RE, IM, H00, H01, H10, H11);
    } else {
        gate_local<8>(RE, IM, G00, G01, G10, G11);
    }
}

__global__ __launch_bounds__(128, 4)
void qsim_kernel(const float* __restrict__ x, const float* __restrict__ w,
                 float* __restrict__ out, int B) {
    // In-block gate setup: threads 0..17 build M = RZ(w2)@RY(w1)@RZ(w0).
    __shared__ float2 sM[NL * NQ * 4];
    {
        int g = threadIdx.x;
        if (g < NL * NQ) {
            float w0 = w[g * 3 + 0];
            float w1 = w[g * 3 + 1];
            float w2 = w[g * 3 + 2];
            float s1, c1, sp_, cp_, sm2, cm2;
            sincosf(0.5f * w1, &s1, &c1);
            sincosf(0.5f * (w0 + w2), &sp_, &cp_);
            sincosf(0.5f * (w0 - w2), &sm2, &cm2);
            sM[g * 4 + 0] = make_float2(c1 * cp_, -c1 * sp_);   // M00
            sM[g * 4 + 1] = make_float2(-s1 * cm2, -s1 * sm2);  // M01
            sM[g * 4 + 2] = make_float2(s1 * cm2, -s1 * sm2);   // M10
            sM[g * 4 + 3] = make_float2(c1 * cp_, c1 * sp_);    // M11
        }
    }
    __syncthreads();

    int tid = blockIdx.x * blockDim.x + threadIdx.x;
    int b = tid >> 1;
    if (b >= B) return;
    int p = tid & 1;  // this thread's wire-0 (MSB) value

    // Vectorized x load, then angles.
    float cs[NQ], sn[NQ];
    {
        const float2* xx = reinterpret_cast<const float2*>(x + (size_t)b * NQ);
        float2 x01 = xx[0], x23 = xx[1], x45 = xx[2];
        float xv[NQ] = {x01.x, x01.y, x23.x, x23.y, x45.x, x45.y};
#pragma unroll
        for (int q = 0; q < NQ; q++) {
            float t = 1.5707963267948966f * tanh_fast(xv[q]);
            __sincosf(t, &sn[q], &cs[q]);
        }
    }

    // 32 local amps packed: RE[K] = (re_{2K}, re_{2K+1}), pack lane = wire5.
    // Pack-index bits k3..k0 = wires 1..4.
    ull RE[16], IM[16];

    // ---- Layer 0: product state |0..0> -> tensor of first gate columns.
    //      Ring0's cnot(0,1) folded into the wire-1 factor (v0<->v1 for p=1). ----
    {
        float2 a;  // wire-0 factor for this thread
        {
            float2 ma = p ? sM[2] : sM[0];
            float2 mb = p ? sM[3] : sM[1];
            a.x = fmaf(cs[0], ma.x, sn[0] * mb.x);
            a.y = fmaf(cs[0], ma.y, sn[0] * mb.y);
        }
        {
            float2 m00 = sM[5 * 4 + 0], m01 = sM[5 * 4 + 1];
            float2 m10 = sM[5 * 4 + 2], m11 = sM[5 * 4 + 3];
            float2 v0 = make_float2(fmaf(cs[5], m00.x, sn[5] * m01.x),
                                    fmaf(cs[5], m00.y, sn[5] * m01.y));
            float2 v1 = make_float2(fmaf(cs[5], m10.x, sn[5] * m11.x),
                                    fmaf(cs[5], m10.y, sn[5] * m11.y));
            ull V5X = pk(v0.x, v1.x), V5Y = pk(v0.y, v1.y), V5Yn = pk(-v0.y, -v1.y);
            RE[0] = fma2(sp2(a.x), V5X, mul2(sp2(a.y), V5Yn));
            IM[0] = fma2(sp2(a.x), V5Y, mul2(sp2(a.y), V5X));
        }
#pragma unroll
        for (int q = 1; q <= 4; q++) {
            float2 m00 = sM[q * 4 + 0], m01 = sM[q * 4 + 1];
            float2 m10 = sM[q * 4 + 2], m11 = sM[q * 4 + 3];
            float2 v0 = make_float2(fmaf(cs[q], m00.x, sn[q] * m01.x),
                                    fmaf(cs[q], m00.y, sn[q] * m01.y));
            float2 v1 = make_float2(fmaf(cs[q], m10.x, sn[q] * m11.x),
                                    fmaf(cs[q], m10.y, sn[q] * m11.y));
            if (q == 1) {
                float2 t0 = v0, t1 = v1;
                v0 = p ? t1 : t0;
                v1 = p ? t0 : t1;
            }
            ull x0 = sp2(v0.x), ny0 = sp2(-v0.y), y0 = sp2(v0.y);
            ull x1 = sp2(v1.x), ny1 = sp2(-v1.y), y1 = sp2(v1.y);
            int n = 1 << (q - 1);
#pragma unroll
            for (int k = 15; k >= 0; k--) {
                if (k < n) {
                    ull r = RE[k], i = IM[k];
                    RE[2 * k + 1] = fma2(x1, r, mul2(ny1, i));
                    IM[2 * k + 1] = fma2(x1, i, mul2(y1, r));
                    RE[2 * k]     = fma2(x0, r, mul2(ny0, i));
                    IM[2 * k]     = fma2(x0, i, mul2(y0, r));
                }
            }
        }
    }
    cnot_ring_rest(RE, IM);  // ring0: (1,2)(2,3)(3,4)(4,5); cnot(5,0) pending

    // ---- Layer 1: gates + ring1 (cnot(0,1) folded into w1; (5,0) pending) ----
    apply_gates(RE, IM, &sM[1 * NQ * 4], cs, sn, p, /*fold_w1=*/true);
    cnot_ring_rest(RE, IM);

    // ---- Layer 2 (final): gates only. The ENTIRE final ring is folded into
    //      the readout sign permutation below (w1 plain, no ring). ----
    apply_gates(RE, IM, &sM[2 * NQ * 4], cs, sn, p, /*fold_w1=*/false);

    // ---- Readout with final-ring fold.
    // Final ring maps bit q -> prefix parity b0^..^bq (b0 -> b1^..^b5), so:
    //   e1 = (-1)^p * Walsh{k3},          e2 = (-1)^p * Walsh{k3,k2},
    //   e3 = (-1)^p * Walsh{k3,k2,k1},    e4 = (-1)^p * Walsh{k3..k0},
    //   e5 = (-1)^p * lanediff(Walsh{k3..k0}),  e0 = lanediff(Walsh{k3..k0}).
    // Subtractions via fma2(-1, b, a): single fma-pipe op each. ----
    const ull MONE = sp2(-1.0f);
    ull PR[16];
#pragma unroll
    for (int K = 0; K < 16; K++) {
        PR[K] = fma2(RE[K], RE[K], mul2(IM[K], IM[K]));
    }
    // L0 over k0
    ull A[8], D[8];
#pragma unroll
    for (int j = 0; j < 8; j++) {
        A[j] = add2(PR[2 * j], PR[2 * j + 1]);
        D[j] = sub2f(PR[2 * j], PR[2 * j + 1], MONE);
    }
    // L1 over k1
    ull S[4], U[4], V[4];
#pragma unroll
    for (int i = 0; i < 4; i++) {
        S[i] = add2(A[2 * i], A[2 * i + 1]);
        U[i] = sub2f(A[2 * i], A[2 * i + 1], MONE);
        V[i] = sub2f(D[2 * i], D[2 * i + 1], MONE);
    }
    // L2 over k2
    ull S2[2], W2[2], U2[2], V2[2];
#pragma unroll
    for (int m = 0; m < 2; m++) {
        S2[m] = add2(S[2 * m], S[2 * m + 1]);
        W2[m] = sub2f(S[2 * m], S[2 * m + 1], MONE);
        U2[m] = sub2f(U[2 * m], U[2 * m + 1], MONE);
        V2[m] = sub2f(V[2 * m], V[2 * m + 1], MONE);
    }
    // L3 over k3
    ull E1v = sub2f(S2[0], S2[1], MONE);   // Walsh{k3}
    ull E2v = sub2f(W2[0], W2[1], MONE);   // Walsh{k3,k2}
    ull E3v = sub2f(U2[0], U2[1], MONE);   // Walsh{k3,k2,k1}
    ull E4v = sub2f(V2[0], V2[1], MONE);   // Walsh{k3,k2,k1,k0}

    float sg = p ? -1.0f : 1.0f;
    float e1 = sg * (flo(E1v) + fhi(E1v));
    float e2 = sg * (flo(E2v) + fhi(E2v));
    float e3 = sg * (flo(E3v) + fhi(E3v));
    float e4 = sg * (flo(E4v) + fhi(E4v));
    float g5 = flo(E4v) - fhi(E4v);
    float e5 = sg * g5;
    float e0 = g5;  // no p factor (b0 cancels in its own prefix parity)

    e0 += __shfl_xor_sync(0xffffffffu, e0, 1);
    e1 += __shfl_xor_sync(0xffffffffu, e1, 1);
    e2 += __shfl_xor_sync(0xffffffffu, e2, 1);
    e3 += __shfl_xor_sync(0xffffffffu, e3, 1);
    e4 += __shfl_xor_sync(0xffffffffu, e4, 1);
    e5 += __shfl_xor_sync(0xffffffffu, e5, 1);

    // Vectorized stores: b*6 floats = 24B base (8B-aligned).
    float* ob = out + (size_t)b * NQ;
    if (p == 0) {
        *reinterpret_cast<float2*>(ob) = make_float2(e0, e1);  // ob[0..1]
        ob[2] = e2;
    } else {
        ob[3] = e3;
        *reinterpret_cast<float2*>(ob + 4) = make_float2(e4, e5);  // ob[4..5]
    }
}

extern "C" void kernel_launch(void* const* d_in, const int* in_sizes, int n_in,
                              void* d_out, int out_size) {
    const float* x = (const float*)d_in[0];
    const float* w = (const float*)d_in[1];
    float* out = (float*)d_out;
    int B = in_sizes[0] / NQ;

    const int threads = 128;
    long long total = 2LL * B;
    int blocks = (int)((total + threads - 1) / threads);
    qsim_kernel<<<blocks, threads>>>(x, w, out, B);
}

// round 13
// speedup vs baseline: 1.2180x; 1.0040x over previous
#include <cuda_runtime.h>

#define NQ 6
#define NL 3

typedef unsigned long long ull;

// ---- packed f32x2 helpers ----
__device__ __forceinline__ ull fma2(ull a, ull b, ull c) {
    ull d; asm("fma.rn.f32x2 %0,%1,%2,%3;" : "=l"(d) : "l"(a), "l"(b), "l"(c)); return d;
}
__device__ __forceinline__ ull mul2(ull a, ull b) {
    ull d; asm("mul.rn.f32x2 %0,%1,%2;" : "=l"(d) : "l"(a), "l"(b)); return d;
}
__device__ __forceinline__ ull add2(ull a, ull b) {
    ull d; asm("add.rn.f32x2 %0,%1,%2;" : "=l"(d) : "l"(a), "l"(b)); return d;
}
__device__ __forceinline__ ull pk(float lo, float hi) {
    ull d; asm("mov.b64 %0,{%1,%2};" : "=l"(d) : "f"(lo), "f"(hi)); return d;
}
__device__ __forceinline__ ull sp2(float x) { return pk(x, x); }
__device__ __forceinline__ float flo(ull v) { return __uint_as_float((unsigned)v); }
__device__ __forceinline__ float fhi(ull v) { return __uint_as_float((unsigned)(v >> 32)); }
__device__ __forceinline__ ull lsw(ull v) { return pk(fhi(v), flo(v)); }     // lane swap
__device__ __forceinline__ float tanh_fast(float x) {
    float y; asm("tanh.approx.f32 %0, %1;" : "=f"(y) : "f"(x)); return y;
}
// a - b on the fma pipe (1 op)
__device__ __forceinline__ ull sub2f(ull a, ull b, ull MONE) { return fma2(MONE, b, a); }

// Gate on local wire w in {1..4}: pack-index stride S = 1<<(4-w). Element-wise packed.
template <int S>
__device__ __forceinline__ void gate_local(ull* RE, ull* IM,
                                           float2 G00, float2 G01, float2 G10, float2 G11) {
    ull x00 = sp2(G00.x), ny00 = sp2(-G00.y), y00 = sp2(G00.y);
    ull x01 = sp2(G01.x), ny01 = sp2(-G01.y), y01 = sp2(G01.y);
    ull x10 = sp2(G10.x), ny10 = sp2(-G10.y), y10 = sp2(G10.y);
    ull x11 = sp2(G11.x), ny11 = sp2(-G11.y), y11 = sp2(G11.y);
#pragma unroll
    for (int t = 0; t < 8; t++) {
        int K0 = ((t & ~(S - 1)) << 1) | (t & (S - 1));
        int K1 = K0 + S;
        ull r0 = RE[K0], i0 = IM[K0], r1 = RE[K1], i1 = IM[K1];
        RE[K0] = fma2(x00, r0, fma2(ny00, i0, fma2(x01, r1, mul2(ny01, i1))));
        IM[K0] = fma2(x00, i0, fma2(y00, r0, fma2(x01, i1, mul2(y01, r1))));
        RE[K1] = fma2(x10, r0, fma2(ny10, i0, fma2(x11, r1, mul2(ny11, i1))));
        IM[K1] = fma2(x10, i0, fma2(y10, r0, fma2(x11, i1, mul2(y11, r1))));
    }
}

// Gate on wire 5 (the two lanes inside each pack), swap-form:
// out = P .* st + Q .* laneswap(st), P=(G00,G11), Q=(G01,G10).
__device__ __forceinline__ void gate_w5(ull* RE, ull* IM,
                                        float2 G00, float2 G01, float2 G10, float2 G11) {
    ull Px = pk(G00.x, G11.x), Py = pk(G00.y, G11.y), nPy = pk(-G00.y, -G11.y);
    ull Qx = pk(G01.x, G10.x), Qy = pk(G01.y, G10.y), nQy = pk(-G01.y, -G10.y);
#pragma unroll
    for (int K = 0; K < 16; K++) {
        ull r = RE[K], i = IM[K];
        ull rs = lsw(r), is = lsw(i);
        RE[K] = fma2(Px, r, fma2(nPy, i, fma2(Qx, rs, mul2(nQy, is))));
        IM[K] = fma2(Px, i, fma2(Py, r, fma2(Qx, is, mul2(Qy, rs))));
    }
}

// Wire-5 gate with the ring's cnot(4,5) FOLDED in (odd K gets post-lane-swap).
// Odd-K outputs are lsw(normal): implemented with lane-swapped coefficient
// packs (built by packing scalars in the other order — zero extra ops).
// Even and odd K processed in separate subloops to keep register pressure low.
__device__ __forceinline__ void gate_w5_foldC45(ull* RE, ull* IM,
                                                float2 G00, float2 G01, float2 G10, float2 G11) {
    {   // even K: normal coefficients
        ull Px = pk(G00.x, G11.x), Py = pk(G00.y, G11.y), nPy = pk(-G00.y, -G11.y);
        ull Qx = pk(G01.x, G10.x), Qy = pk(G01.y, G10.y), nQy = pk(-G01.y, -G10.y);
#pragma unroll
        for (int K = 0; K < 16; K += 2) {
            ull r = RE[K], i = IM[K];
            ull rs = lsw(r), is = lsw(i);
            RE[K] = fma2(Px, r, fma2(nPy, i, fma2(Qx, rs, mul2(nQy, is))));
            IM[K] = fma2(Px, i, fma2(Py, r, fma2(Qx, is, mul2(Qy, rs))));
        }
    }
    {   // odd K: out' = lsw(out) via lane-swapped packs:
        //   re' = oQx.r + onQy.i + oPx.rs + onPy.is
        //   im' = oQx.i + oQy.r  + oPx.is + oPy.rs
        ull oPx = pk(G11.x, G00.x), oPy = pk(G11.y, G00.y), onPy = pk(-G11.y, -G00.y);
        ull oQx = pk(G10.x, G01.x), oQy = pk(G10.y, G01.y), onQy = pk(-G10.y, -G01.y);
#pragma unroll
        for (int K = 1; K < 16; K += 2) {
            ull r = RE[K], i = IM[K];
            ull rs = lsw(r), is = lsw(i);
            RE[K] = fma2(oQx, r, fma2(onQy, i, fma2(oPx, rs, mul2(onPy, is))));
            IM[K] = fma2(oQx, i, fma2(oQy, r, fma2(oPx, is, mul2(oPy, rs))));
        }
    }
}

// Gate on wire 0 fused with a PENDING cnot(5,0) from the preceding ring.
// Asymmetric coefficient packs absorb the lane merge; 2-deep SHFL pipeline.
__device__ __forceinline__ void gate_w0_fused(ull* RE, ull* IM, float2 Gd, float2 Go) {
    ull dx = pk(Gd.x, Go.x), ox = pk(Go.x, Gd.x);
    ull dy = pk(Gd.y, Go.y), oy = pk(Go.y, Gd.y);
    ull ndy = pk(-Gd.y, -Go.y), noy = pk(-Go.y, -Gd.y);
    ull pr = __shfl_xor_sync(0xffffffffu, RE[0], 1);
    ull pi = __shfl_xor_sync(0xffffffffu, IM[0], 1);
#pragma unroll
    for (int K = 0; K < 16; K++) {
        ull prn = 0, pin = 0;
        if (K < 15) {
            prn = __shfl_xor_sync(0xffffffffu, RE[K + 1], 1);
            pin = __shfl_xor_sync(0xffffffffu, IM[K + 1], 1);
        }
        ull r = RE[K], i = IM[K];
        RE[K] = fma2(dx, r, fma2(ndy, i, fma2(ox, pr, mul2(noy, pi))));
        IM[K] = fma2(dx, i, fma2(dy, r, fma2(ox, pi, mul2(oy, pr))));
        pr = prn; pi = pin;
    }
}

__device__ __forceinline__ void swp(ull& a, ull& b) { ull t = a; a = b; b = t; }

// Free pack-index renames: cnot(1,2)(2,3)(3,4).
__device__ __forceinline__ void cnot_free_swaps(ull* RE, ull* IM) {
    // cnot(1,2): bit3==1 -> flip bit2
    swp(RE[8], RE[12]); swp(IM[8], IM[12]);
    swp(RE[9], RE[13]); swp(IM[9], IM[13]);
    swp(RE[10], RE[14]); swp(IM[10], IM[14]);
    swp(RE[11], RE[15]); swp(IM[11], IM[15]);
    // cnot(2,3): bit2==1 -> flip bit1
    swp(RE[4], RE[6]);  swp(IM[4], IM[6]);
    swp(RE[5], RE[7]);  swp(IM[5], IM[7]);
    swp(RE[12], RE[14]); swp(IM[12], IM[14]);
    swp(RE[13], RE[15]); swp(IM[13], IM[15]);
    // cnot(3,4): bit1==1 -> flip bit0
    swp(RE[2], RE[3]);  swp(IM[2], IM[3]);
    swp(RE[6], RE[7]);  swp(IM[6], IM[7]);
    swp(RE[10], RE[11]); swp(IM[10], IM[11]);
    swp(RE[14], RE[15]); swp(IM[14], IM[15]);
}

// Ring0 tail: free swaps + explicit cnot(4,5) lane swap on odd packs.
__device__ __forceinline__ void cnot_ring_rest(ull* RE, ull* IM) {
    cnot_free_swaps(RE, IM);
#pragma unroll
    for (int K = 1; K < 16; K += 2) {
        RE[K] = lsw(RE[K]);
        IM[K] = lsw(IM[K]);
    }
}

// Gate coefficient build; M loaded as 2x float4 (16B LDS), sM is 16B-aligned.
__device__ __forceinline__ void makeG(const float2* m, float c, float s,
                                      float2& G00, float2& G01, float2& G10, float2& G11) {
    const float4* m4 = reinterpret_cast<const float4*>(m);
    float4 a = m4[0], bb = m4[1];
    float2 m00 = make_float2(a.x, a.y), m01 = make_float2(a.z, a.w);
    float2 m10 = make_float2(bb.x, bb.y), m11 = make_float2(bb.z, bb.w);
    G00.x = fmaf(c, m00.x, s * m01.x);  G00.y = fmaf(c, m00.y, s * m01.y);
    G01.x = fmaf(-s, m00.x, c * m01.x); G01.y = fmaf(-s, m00.y, c * m01.y);
    G10.x = fmaf(c, m10.x, s * m11.x);  G10.y = fmaf(c, m10.y, s * m11.y);
    G11.x = fmaf(-s, m10.x, c * m11.x); G11.y = fmaf(-s, m10.y, c * m11.y);
}

__global__ __launch_bounds__(128, 4)
void qsim_kernel(const float* __restrict__ x, const float* __restrict__ w,
                 float* __restrict__ out, int B) {
    // In-block gate setup: threads 0..17 build M = RZ(w2)@RY(w1)@RZ(w0).
    __shared__ __align__(16) float2 sM[NL * NQ * 4];
    {
        int g = threadIdx.x;
        if (g < NL * NQ) {
            float w0 = w[g * 3 + 0];
            float w1 = w[g * 3 + 1];
            float w2 = w[g * 3 + 2];
            float s1, c1, sp_, cp_, sm2, cm2;
            sincosf(0.5f * w1, &s1, &c1);
            sincosf(0.5f * (w0 + w2), &sp_, &cp_);
            sincosf(0.5f * (w0 - w2), &sm2, &cm2);
            sM[g * 4 + 0] = make_float2(c1 * cp_, -c1 * sp_);   // M00
            sM[g * 4 + 1] = make_float2(-s1 * cm2, -s1 * sm2);  // M01
            sM[g * 4 + 2] = make_float2(s1 * cm2, -s1 * sm2);   // M10
            sM[g * 4 + 3] = make_float2(c1 * cp_, c1 * sp_);    // M11
        }
    }
    __syncthreads();

    int tid = blockIdx.x * blockDim.x + threadIdx.x;
    int b = tid >> 1;
    if (b >= B) return;
    int p = tid & 1;  // this thread's wire-0 (MSB) value

    // Vectorized x load, then angles.
    float cs[NQ], sn[NQ];
    {
        const float2* xx = reinterpret_cast<const float2*>(x + (size_t)b * NQ);
        float2 x01 = xx[0], x23 = xx[1], x45 = xx[2];
        float xv[NQ] = {x01.x, x01.y, x23.x, x23.y, x45.x, x45.y};
#pragma unroll
        for (int q = 0; q < NQ; q++) {
            float t = 1.5707963267948966f * tanh_fast(xv[q]);
            __sincosf(t, &sn[q], &cs[q]);
        }
    }

    // 32 local amps packed: RE[K] = (re_{2K}, re_{2K+1}), pack lane = wire5.
    // Pack-index bits k3..k0 = wires 1..4.
    ull RE[16], IM[16];

    // ---- Layer 0: product state |0..0> -> tensor of first gate columns.
    //      Ring0's cnot(0,1) folded into the wire-1 factor (v0<->v1 for p=1). ----
    {
        float2 a;  // wire-0 factor for this thread
        {
            float2 ma = p ? sM[2] : sM[0];
            float2 mb = p ? sM[3] : sM[1];
            a.x = fmaf(cs[0], ma.x, sn[0] * mb.x);
            a.y = fmaf(cs[0], ma.y, sn[0] * mb.y);
        }
        {
            float2 m00 = sM[5 * 4 + 0], m01 = sM[5 * 4 + 1];
            float2 m10 = sM[5 * 4 + 2], m11 = sM[5 * 4 + 3];
            float2 v0 = make_float2(fmaf(cs[5], m00.x, sn[5] * m01.x),
                                    fmaf(cs[5], m00.y, sn[5] * m01.y));
            float2 v1 = make_float2(fmaf(cs[5], m10.x, sn[5] * m11.x),
                                    fmaf(cs[5], m10.y, sn[5] * m11.y));
            ull V5X = pk(v0.x, v1.x), V5Y = pk(v0.y, v1.y), V5Yn = pk(-v0.y, -v1.y);
            RE[0] = fma2(sp2(a.x), V5X, mul2(sp2(a.y), V5Yn));
            IM[0] = fma2(sp2(a.x), V5Y, mul2(sp2(a.y), V5X));
        }
#pragma unroll
        for (int q = 1; q <= 4; q++) {
            float2 m00 = sM[q * 4 + 0], m01 = sM[q * 4 + 1];
            float2 m10 = sM[q * 4 + 2], m11 = sM[q * 4 + 3];
            float2 v0 = make_float2(fmaf(cs[q], m00.x, sn[q] * m01.x),
                                    fmaf(cs[q], m00.y, sn[q] * m01.y));
            float2 v1 = make_float2(fmaf(cs[q], m10.x, sn[q] * m11.x),
                                    fmaf(cs[q], m10.y, sn[q] * m11.y));
            if (q == 1) {
                float2 t0 = v0, t1 = v1;
                v0 = p ? t1 : t0;
                v1 = p ? t0 : t1;
            }
            ull x0 = sp2(v0.x), ny0 = sp2(-v0.y), y0 = sp2(v0.y);
            ull x1 = sp2(v1.x), ny1 = sp2(-v1.y), y1 = sp2(v1.y);
            int n = 1 << (q - 1);
#pragma unroll
            for (int k = 15; k >= 0; k--) {
                if (k < n) {
                    ull r = RE[k], i = IM[k];
                    RE[2 * k + 1] = fma2(x1, r, mul2(ny1, i));
                    IM[2 * k + 1] = fma2(x1, i, mul2(y1, r));
                    RE[2 * k]     = fma2(x0, r, mul2(ny0, i));
                    IM[2 * k]     = fma2(x0, i, mul2(y0, r));
                }
            }
        }
    }
    cnot_ring_rest(RE, IM);  // ring0: (1,2)(2,3)(3,4)(4,5); cnot(5,0) pending

    // ---- Layer 1: w0(C50 fused), w2..w4, w1(C01 fold), free swaps, then
    //      w5 with cnot(4,5) FOLDED (legal: G5 commutes with C01,C12,C23,C34).
    //      Leaves cnot(5,0) pending. ----
    {
        const float2* mbase = &sM[1 * NQ * 4];
        float2 G00, G01, G10, G11;
        {
            float2 ma = p ? mbase[2] : mbase[0];
            float2 mb = p ? mbase[3] : mbase[1];
            float c = cs[0], s = sn[0];
            float2 u = make_float2(fmaf(c, ma.x, s * mb.x), fmaf(c, ma.y, s * mb.y));
            float2 v = make_float2(fmaf(-s, ma.x, c * mb.x), fmaf(-s, ma.y, c * mb.y));
            float2 Gd = p ? v : u;
            float2 Go = p ? u : v;
            gate_w0_fused(RE, IM, Gd, Go);
        }
        makeG(mbase + 8, cs[2], sn[2], G00, G01, G10, G11);
        gate_local<4>(RE, IM, G00, G01, G10, G11);
        makeG(mbase + 12, cs[3], sn[3], G00, G01, G10, G11);
        gate_local<2>(RE, IM, G00, G01, G10, G11);
        makeG(mbase + 16, cs[4], sn[4], G00, G01, G10, G11);
        gate_local<1>(RE, IM, G00, G01, G10, G11);
        // w1 with cnot(0,1) folded (X^p row swap)
        makeG(mbase + 4, cs[1], sn[1], G00, G01, G10, G11);
        {
            float2 H00 = p ? G10 : G00, H01 = p ? G11 : G01;
            float2 H10 = p ? G00 : G10, H11 = p ? G01 : G11;
            gate_local<8>(RE, IM, H00, H01, H10, H11);
        }
        // ring1 free part, then w5 with C45 folded
        cnot_free_swaps(RE, IM);
        makeG(mbase + 20, cs[5], sn[5], G00, G01, G10, G11);
        gate_w5_foldC45(RE, IM, G00, G01, G10, G11);
    }

    // ---- Layer 2 (final): gates only; ENTIRE final ring folded into readout. ----
    {
        const float2* mbase = &sM[2 * NQ * 4];
        float2 G00, G01, G10, G11;
        {
            float2 ma = p ? mbase[2] : mbase[0];
            float2 mb = p ? mbase[3] : mbase[1];
            float c = cs[0], s = sn[0];
            float2 u = make_float2(fmaf(c, ma.x, s * mb.x), fmaf(c, ma.y, s * mb.y));
            float2 v = make_float2(fmaf(-s, ma.x, c * mb.x), fmaf(-s, ma.y, c * mb.y));
            float2 Gd = p ? v : u;
            float2 Go = p ? u : v;
            gate_w0_fused(RE, IM, Gd, Go);
        }
        makeG(mbase + 8, cs[2], sn[2], G00, G01, G10, G11);
        gate_local<4>(RE, IM, G00, G01, G10, G11);
        makeG(mbase + 12, cs[3], sn[3], G00, G01, G10, G11);
        gate_local<2>(RE, IM, G00, G01, G10, G11);
        makeG(mbase + 16, cs[4], sn[4], G00, G01, G10, G11);
        gate_local<1>(RE, IM, G00, G01, G10, G11);
        makeG(mbase + 20, cs[5], sn[5], G00, G01, G10, G11);
        gate_w5(RE, IM, G00, G01, G10, G11);
        makeG(mbase + 4, cs[1], sn[1], G00, G01, G10, G11);
        gate_local<8>(RE, IM, G00, G01, G10, G11);
    }

    // ---- Readout with final-ring fold (prefix-parity Walsh taps). ----
    const ull MONE = sp2(-1.0f);
    ull PR[16];
#pragma unroll
    for (int K = 0; K < 16; K++) {
        PR[K] = fma2(RE[K], RE[K], mul2(IM[K], IM[K]));
    }
    // L0 over k0
    ull A[8], D[8];
#pragma unroll
    for (int j = 0; j < 8; j++) {
        A[j] = add2(PR[2 * j], PR[2 * j + 1]);
        D[j] = sub2f(PR[2 * j], PR[2 * j + 1], MONE);
    }
    // L1 over k1
    ull S[4], U[4], V[4];
#pragma unroll
    for (int i = 0; i < 4; i++) {
        S[i] = add2(A[2 * i], A[2 * i + 1]);
        U[i] = sub2f(A[2 * i], A[2 * i + 1], MONE);
        V[i] = sub2f(D[2 * i], D[2 * i + 1], MONE);
    }
    // L2 over k2
    ull S2[2], W2[2], U2[2], V2[2];
#pragma unroll
    for (int m = 0; m < 2; m++) {
        S2[m] = add2(S[2 * m], S[2 * m + 1]);
        W2[m] = sub2f(S[2 * m], S[2 * m + 1], MONE);
        U2[m] = sub2f(U[2 * m], U[2 * m + 1], MONE);
        V2[m] = sub2f(V[2 * m], V[2 * m + 1], MONE);
    }
    // L3 over k3
    ull E1v = sub2f(S2[0], S2[1], MONE);   // Walsh{k3}
    ull E2v = sub2f(W2[0], W2[1], MONE);   // Walsh{k3,k2}
    ull E3v = sub2f(U2[0], U2[1], MONE);   // Walsh{k3,k2,k1}
    ull E4v = sub2f(V2[0], V2[1], MONE);   // Walsh{k3,k2,k1,k0}

    float sg = p ? -1.0f : 1.0f;
    float e1 = sg * (flo(E1v) + fhi(E1v));
    float e2 = sg * (flo(E2v) + fhi(E2v));
    float e3 = sg * (flo(E3v) + fhi(E3v));
    float e4 = sg * (flo(E4v) + fhi(E4v));
    float g5 = flo(E4v) - fhi(E4v);
    float e5 = sg * g5;
    float e0 = g5;

    e0 += __shfl_xor_sync(0xffffffffu, e0, 1);
    e1 += __shfl_xor_sync(0xffffffffu, e1, 1);
    e2 += __shfl_xor_sync(0xffffffffu, e2, 1);
    e3 += __shfl_xor_sync(0xffffffffu, e3, 1);
    e4 += __shfl_xor_sync(0xffffffffu, e4, 1);
    e5 += __shfl_xor_sync(0xffffffffu, e5, 1);

    float* ob = out + (size_t)b * NQ;
    if (p == 0) {
        *reinterpret_cast<float2*>(ob) = make_float2(e0, e1);
        ob[2] = e2;
    } else {
        ob[3] = e3;
        *reinterpret_cast<float2*>(ob + 4) = make_float2(e4, e5);
    }
}

extern "C" void kernel_launch(void* const* d_in, const int* in_sizes, int n_in,
                              void* d_out, int out_size) {
    const float* x = (const float*)d_in[0];
    const float* w = (const float*)d_in[1];
    float* out = (float*)d_out;
    int B = in_sizes[0] / NQ;

    const int threads = 128;
    long long total = 2LL * B;
    int blocks = (int)((total + threads - 1) / threads);
    qsim_kernel<<<blocks, threads>>>(x, w, out, B);
}

// round 15
// speedup vs baseline: 1.2544x; 1.0299x over previous
#include <cuda_runtime.h>

#define NQ 6
#define NL 3

typedef unsigned long long ull;

// ---- packed f32x2 helpers ----
__device__ __forceinline__ ull fma2(ull a, ull b, ull c) {
    ull d; asm("fma.rn.f32x2 %0,%1,%2,%3;" : "=l"(d) : "l"(a), "l"(b), "l"(c)); return d;
}
__device__ __forceinline__ ull mul2(ull a, ull b) {
    ull d; asm("mul.rn.f32x2 %0,%1,%2;" : "=l"(d) : "l"(a), "l"(b)); return d;
}
__device__ __forceinline__ ull add2(ull a, ull b) {
    ull d; asm("add.rn.f32x2 %0,%1,%2;" : "=l"(d) : "l"(a), "l"(b)); return d;
}
__device__ __forceinline__ ull pk(float lo, float hi) {
    ull d; asm("mov.b64 %0,{%1,%2};" : "=l"(d) : "f"(lo), "f"(hi)); return d;
}
__device__ __forceinline__ ull sp2(float x) { return pk(x, x); }
__device__ __forceinline__ float flo(ull v) { return __uint_as_float((unsigned)v); }
__device__ __forceinline__ float fhi(ull v) { return __uint_as_float((unsigned)(v >> 32)); }
__device__ __forceinline__ ull lsw(ull v) { return pk(fhi(v), flo(v)); }     // lane swap
__device__ __forceinline__ float tanh_fast(float x) {
    float y; asm("tanh.approx.f32 %0, %1;" : "=f"(y) : "f"(x)); return y;
}
// a - b on the fma pipe (1 op)
__device__ __forceinline__ ull sub2f(ull a, ull b, ull MONE) { return fma2(MONE, b, a); }

// Gate on local wire w in {1..4}: pack-index stride S = 1<<(4-w). Element-wise packed.
template <int S>
__device__ __forceinline__ void gate_local(ull* RE, ull* IM,
                                           float2 G00, float2 G01, float2 G10, float2 G11) {
    ull x00 = sp2(G00.x), ny00 = sp2(-G00.y), y00 = sp2(G00.y);
    ull x01 = sp2(G01.x), ny01 = sp2(-G01.y), y01 = sp2(G01.y);
    ull x10 = sp2(G10.x), ny10 = sp2(-G10.y), y10 = sp2(G10.y);
    ull x11 = sp2(G11.x), ny11 = sp2(-G11.y), y11 = sp2(G11.y);
#pragma unroll
    for (int t = 0; t < 8; t++) {
        int K0 = ((t & ~(S - 1)) << 1) | (t & (S - 1));
        int K1 = K0 + S;
        ull r0 = RE[K0], i0 = IM[K0], r1 = RE[K1], i1 = IM[K1];
        RE[K0] = fma2(x00, r0, fma2(ny00, i0, fma2(x01, r1, mul2(ny01, i1))));
        IM[K0] = fma2(x00, i0, fma2(y00, r0, fma2(x01, i1, mul2(y01, r1))));
        RE[K1] = fma2(x10, r0, fma2(ny10, i0, fma2(x11, r1, mul2(ny11, i1))));
        IM[K1] = fma2(x10, i0, fma2(y10, r0, fma2(x11, i1, mul2(y11, r1))));
    }
}

// Gate on wire 5 (the two lanes inside each pack), swap-form:
// out = P .* st + Q .* laneswap(st), P=(G00,G11), Q=(G01,G10).
__device__ __forceinline__ void gate_w5(ull* RE, ull* IM,
                                        float2 G00, float2 G01, float2 G10, float2 G11) {
    ull Px = pk(G00.x, G11.x), Py = pk(G00.y, G11.y), nPy = pk(-G00.y, -G11.y);
    ull Qx = pk(G01.x, G10.x), Qy = pk(G01.y, G10.y), nQy = pk(-G01.y, -G10.y);
#pragma unroll
    for (int K = 0; K < 16; K++) {
        ull r = RE[K], i = IM[K];
        ull rs = lsw(r), is = lsw(i);
        RE[K] = fma2(Px, r, fma2(nPy, i, fma2(Qx, rs, mul2(nQy, is))));
        IM[K] = fma2(Px, i, fma2(Py, r, fma2(Qx, is, mul2(Qy, rs))));
    }
}

// Wire-5 gate with the ring's cnot(4,5) FOLDED in (odd K gets post-lane-swap,
// realized with lane-swapped coefficient packs — zero extra ops).
__device__ __forceinline__ void gate_w5_foldC45(ull* RE, ull* IM,
                                                float2 G00, float2 G01, float2 G10, float2 G11) {
    {   // even K: normal coefficients
        ull Px = pk(G00.x, G11.x), Py = pk(G00.y, G11.y), nPy = pk(-G00.y, -G11.y);
        ull Qx = pk(G01.x, G10.x), Qy = pk(G01.y, G10.y), nQy = pk(-G01.y, -G10.y);
#pragma unroll
        for (int K = 0; K < 16; K += 2) {
            ull r = RE[K], i = IM[K];
            ull rs = lsw(r), is = lsw(i);
            RE[K] = fma2(Px, r, fma2(nPy, i, fma2(Qx, rs, mul2(nQy, is))));
            IM[K] = fma2(Px, i, fma2(Py, r, fma2(Qx, is, mul2(Qy, rs))));
        }
    }
    {   // odd K: out' = lsw(out) via lane-swapped packs
        ull oPx = pk(G11.x, G00.x), oPy = pk(G11.y, G00.y), onPy = pk(-G11.y, -G00.y);
        ull oQx = pk(G10.x, G01.x), oQy = pk(G10.y, G01.y), onQy = pk(-G10.y, -G01.y);
#pragma unroll
        for (int K = 1; K < 16; K += 2) {
            ull r = RE[K], i = IM[K];
            ull rs = lsw(r), is = lsw(i);
            RE[K] = fma2(oQx, r, fma2(onQy, i, fma2(oPx, rs, mul2(onPy, is))));
            IM[K] = fma2(oQx, i, fma2(oQy, r, fma2(oPx, is, mul2(oPy, rs))));
        }
    }
}

// Gate on wire 0 fused with a PENDING cnot(5,0) from the preceding ring.
// Asymmetric coefficient packs absorb the lane merge; 2-deep SHFL pipeline.
__device__ __forceinline__ void gate_w0_fused(ull* RE, ull* IM, float2 Gd, float2 Go) {
    ull dx = pk(Gd.x, Go.x), ox = pk(Go.x, Gd.x);
    ull dy = pk(Gd.y, Go.y), oy = pk(Go.y, Gd.y);
    ull ndy = pk(-Gd.y, -Go.y), noy = pk(-Go.y, -Gd.y);
    ull pr = __shfl_xor_sync(0xffffffffu, RE[0], 1);
    ull pi = __shfl_xor_sync(0xffffffffu, IM[0], 1);
#pragma unroll
    for (int K = 0; K < 16; K++) {
        ull prn = 0, pin = 0;
        if (K < 15) {
            prn = __shfl_xor_sync(0xffffffffu, RE[K + 1], 1);
            pin = __shfl_xor_sync(0xffffffffu, IM[K + 1], 1);
        }
        ull r = RE[K], i = IM[K];
        RE[K] = fma2(dx, r, fma2(ndy, i, fma2(ox, pr, mul2(noy, pi))));
        IM[K] = fma2(dx, i, fma2(dy, r, fma2(ox, pi, mul2(oy, pr))));
        pr = prn; pi = pin;
    }
}

__device__ __forceinline__ void swp(ull& a, ull& b) { ull t = a; a = b; b = t; }

// Free pack-index renames: cnot(1,2)(2,3)(3,4).
__device__ __forceinline__ void cnot_free_swaps(ull* RE, ull* IM) {
    swp(RE[8], RE[12]); swp(IM[8], IM[12]);
    swp(RE[9], RE[13]); swp(IM[9], IM[13]);
    swp(RE[10], RE[14]); swp(IM[10], IM[14]);
    swp(RE[11], RE[15]); swp(IM[11], IM[15]);
    swp(RE[4], RE[6]);  swp(IM[4], IM[6]);
    swp(RE[5], RE[7]);  swp(IM[5], IM[7]);
    swp(RE[12], RE[14]); swp(IM[12], IM[14]);
    swp(RE[13], RE[15]); swp(IM[13], IM[15]);
    swp(RE[2], RE[3]);  swp(IM[2], IM[3]);
    swp(RE[6], RE[7]);  swp(IM[6], IM[7]);
    swp(RE[10], RE[11]); swp(IM[10], IM[11]);
    swp(RE[14], RE[15]); swp(IM[14], IM[15]);
}

// Ring0 tail: free swaps + explicit cnot(4,5) lane swap on odd packs.
__device__ __forceinline__ void cnot_ring_rest(ull* RE, ull* IM) {
    cnot_free_swaps(RE, IM);
#pragma unroll
    for (int K = 1; K < 16; K += 2) {
        RE[K] = lsw(RE[K]);
        IM[K] = lsw(IM[K]);
    }
}

// Gate coefficient build; M loaded as 2x float4 (16B LDS), sM is 16B-aligned.
__device__ __forceinline__ void makeG(const float2* m, float c, float s,
                                      float2& G00, float2& G01, float2& G10, float2& G11) {
    const float4* m4 = reinterpret_cast<const float4*>(m);
    float4 a = m4[0], bb = m4[1];
    float2 m00 = make_float2(a.x, a.y), m01 = make_float2(a.z, a.w);
    float2 m10 = make_float2(bb.x, bb.y), m11 = make_float2(bb.z, bb.w);
    G00.x = fmaf(c, m00.x, s * m01.x);  G00.y = fmaf(c, m00.y, s * m01.y);
    G01.x = fmaf(-s, m00.x, c * m01.x); G01.y = fmaf(-s, m00.y, c * m01.y);
    G10.x = fmaf(c, m10.x, s * m11.x);  G10.y = fmaf(c, m10.y, s * m11.y);
    G11.x = fmaf(-s, m10.x, c * m11.x); G11.y = fmaf(-s, m10.y, c * m11.y);
}

__global__ __launch_bounds__(128, 4)
void qsim_kernel(const float* __restrict__ x, const float* __restrict__ w,
                 float* __restrict__ out, int B) {
    // In-block gate setup: threads 0..17 build M = RZ(w2)@RY(w1)@RZ(w0).
    __shared__ __align__(16) float2 sM[NL * NQ * 4];
    {
        int g = threadIdx.x;
        if (g < NL * NQ) {
            float w0 = w[g * 3 + 0];
            float w1 = w[g * 3 + 1];
            float w2 = w[g * 3 + 2];
            float s1, c1, sp_, cp_, sm2, cm2;
            sincosf(0.5f * w1, &s1, &c1);
            sincosf(0.5f * (w0 + w2), &sp_, &cp_);
            sincosf(0.5f * (w0 - w2), &sm2, &cm2);
            sM[g * 4 + 0] = make_float2(c1 * cp_, -c1 * sp_);   // M00
            sM[g * 4 + 1] = make_float2(-s1 * cm2, -s1 * sm2);  // M01
            sM[g * 4 + 2] = make_float2(s1 * cm2, -s1 * sm2);   // M10
            sM[g * 4 + 3] = make_float2(c1 * cp_, c1 * sp_);    // M11
        }
    }
    __syncthreads();

    int tid = blockIdx.x * blockDim.x + threadIdx.x;
    int b = tid >> 1;
    if (b >= B) return;
    int p = tid & 1;  // this thread's wire-0 (MSB) value

    // Vectorized x load, then angles.
    float cs[NQ], sn[NQ];
    {
        const float2* xx = reinterpret_cast<const float2*>(x + (size_t)b * NQ);
        float2 x01 = xx[0], x23 = xx[1], x45 = xx[2];
        float xv[NQ] = {x01.x, x01.y, x23.x, x23.y, x45.x, x45.y};
#pragma unroll
        for (int q = 0; q < NQ; q++) {
            float t = 1.5707963267948966f * tanh_fast(xv[q]);
            __sincosf(t, &sn[q], &cs[q]);
        }
    }

    // 32 local amps packed: RE[K] = (re_{2K}, re_{2K+1}), pack lane = wire5.
    // Pack-index bits k3..k0 = wires 1..4.
    ull RE[16], IM[16];

    // ---- Layer 0: product state |0..0> -> tensor of first gate columns.
    //      Ring0's cnot(0,1) folded into the wire-1 factor (v0<->v1 for p=1). ----
    {
        float2 a;  // wire-0 factor for this thread
        {
            float2 ma = p ? sM[2] : sM[0];
            float2 mb = p ? sM[3] : sM[1];
            a.x = fmaf(cs[0], ma.x, sn[0] * mb.x);
            a.y = fmaf(cs[0], ma.y, sn[0] * mb.y);
        }
        {
            float2 m00 = sM[5 * 4 + 0], m01 = sM[5 * 4 + 1];
            float2 m10 = sM[5 * 4 + 2], m11 = sM[5 * 4 + 3];
            float2 v0 = make_float2(fmaf(cs[5], m00.x, sn[5] * m01.x),
                                    fmaf(cs[5], m00.y, sn[5] * m01.y));
            float2 v1 = make_float2(fmaf(cs[5], m10.x, sn[5] * m11.x),
                                    fmaf(cs[5], m10.y, sn[5] * m11.y));
            ull V5X = pk(v0.x, v1.x), V5Y = pk(v0.y, v1.y), V5Yn = pk(-v0.y, -v1.y);
            RE[0] = fma2(sp2(a.x), V5X, mul2(sp2(a.y), V5Yn));
            IM[0] = fma2(sp2(a.x), V5Y, mul2(sp2(a.y), V5X));
        }
#pragma unroll
        for (int q = 1; q <= 4; q++) {
            float2 m00 = sM[q * 4 + 0], m01 = sM[q * 4 + 1];
            float2 m10 = sM[q * 4 + 2], m11 = sM[q * 4 + 3];
            float2 v0 = make_float2(fmaf(cs[q], m00.x, sn[q] * m01.x),
                                    fmaf(cs[q], m00.y, sn[q] * m01.y));
            float2 v1 = make_float2(fmaf(cs[q], m10.x, sn[q] * m11.x),
                                    fmaf(cs[q], m10.y, sn[q] * m11.y));
            if (q == 1) {
                float2 t0 = v0, t1 = v1;
                v0 = p ? t1 : t0;
                v1 = p ? t0 : t1;
            }
            ull x0 = sp2(v0.x), ny0 = sp2(-v0.y), y0 = sp2(v0.y);
            ull x1 = sp2(v1.x), ny1 = sp2(-v1.y), y1 = sp2(v1.y);
            int n = 1 << (q - 1);
#pragma unroll
            for (int k = 15; k >= 0; k--) {
                if (k < n) {
                    ull r = RE[k], i = IM[k];
                    RE[2 * k + 1] = fma2(x1, r, mul2(ny1, i));
                    IM[2 * k + 1] = fma2(x1, i, mul2(y1, r));
                    RE[2 * k]     = fma2(x0, r, mul2(ny0, i));
                    IM[2 * k]     = fma2(x0, i, mul2(y0, r));
                }
            }
        }
    }
    cnot_ring_rest(RE, IM);  // ring0: (1,2)(2,3)(3,4)(4,5); cnot(5,0) pending

    // ---- Layer 1: w0(C50 fused), w2..w4, w1(C01 fold), free swaps, then
    //      w5 with cnot(4,5) FOLDED. Leaves cnot(5,0) pending. ----
    {
        const float2* mbase = &sM[1 * NQ * 4];
        float2 G00, G01, G10, G11;
        {
            float2 ma = p ? mbase[2] : mbase[0];
            float2 mb = p ? mbase[3] : mbase[1];
            float c = cs[0], s = sn[0];
            float2 u = make_float2(fmaf(c, ma.x, s * mb.x), fmaf(c, ma.y, s * mb.y));
            float2 v = make_float2(fmaf(-s, ma.x, c * mb.x), fmaf(-s, ma.y, c * mb.y));
            float2 Gd = p ? v : u;
            float2 Go = p ? u : v;
            gate_w0_fused(RE, IM, Gd, Go);
        }
        makeG(mbase + 8, cs[2], sn[2], G00, G01, G10, G11);
        gate_local<4>(RE, IM, G00, G01, G10, G11);
        makeG(mbase + 12, cs[3], sn[3], G00, G01, G10, G11);
        gate_local<2>(RE, IM, G00, G01, G10, G11);
        makeG(mbase + 16, cs[4], sn[4], G00, G01, G10, G11);
        gate_local<1>(RE, IM, G00, G01, G10, G11);
        makeG(mbase + 4, cs[1], sn[1], G00, G01, G10, G11);
        {
            float2 H00 = p ? G10 : G00, H01 = p ? G11 : G01;
            float2 H10 = p ? G00 : G10, H11 = p ? G01 : G11;
            gate_local<8>(RE, IM, H00, H01, H10, H11);
        }
        cnot_free_swaps(RE, IM);
        makeG(mbase + 20, cs[5], sn[5], G00, G01, G10, G11);
        gate_w5_foldC45(RE, IM, G00, G01, G10, G11);
    }

    // ---- Layer 2 (final): w0(C50 fused), w2..w4, w5. The final wire-1 gate
    //      is FUSED into the readout via unitarity (below); the entire final
    //      CNOT ring is folded into the readout sign permutation. ----
    const float2* mbase2 = &sM[2 * NQ * 4];
    {
        float2 G00, G01, G10, G11;
        {
            float2 ma = p ? mbase2[2] : mbase2[0];
            float2 mb = p ? mbase2[3] : mbase2[1];
            float c = cs[0], s = sn[0];
            float2 u = make_float2(fmaf(c, ma.x, s * mb.x), fmaf(c, ma.y, s * mb.y));
            float2 v = make_float2(fmaf(-s, ma.x, c * mb.x), fmaf(-s, ma.y, c * mb.y));
            float2 Gd = p ? v : u;
            float2 Go = p ? u : v;
            gate_w0_fused(RE, IM, Gd, Go);
        }
        makeG(mbase2 + 8, cs[2], sn[2], G00, G01, G10, G11);
        gate_local<4>(RE, IM, G00, G01, G10, G11);
        makeG(mbase2 + 12, cs[3], sn[3], G00, G01, G10, G11);
        gate_local<2>(RE, IM, G00, G01, G10, G11);
        makeG(mbase2 + 16, cs[4], sn[4], G00, G01, G10, G11);
        gate_local<1>(RE, IM, G00, G01, G10, G11);
        makeG(mbase2 + 20, cs[5], sn[5], G00, G01, G10, G11);
        gate_w5(RE, IM, G00, G01, G10, G11);
        // (no w1 gate — fused into DP below)
    }

    // ---- Readout with final-w1-gate fusion + final-ring fold.
    // All outputs are k3-antisymmetric, so only DP[K] = |u|^2 - |v|^2 is
    // needed per (K, K+8) pair, where (u,v) = G1 (a,b). Unitarity of G1:
    //   |u|^2-|v|^2 = alpha*(|a|^2-|b|^2)
    //               + 4*[Re(G00 conjG01)*Re(a conj b) - Im(G00 conjG01)*Im(a conj b)]
    //   alpha = |G00|^2-|G10|^2.
    // (verified on RY/RZ/X/H-like/complex-orthogonal unit cases)
    // Then a 3-level Walsh butterfly on DP (bits b2b1b0 = wires 2,3,4). ----
    const ull MONE = sp2(-1.0f);
    ull tA, tBr, tBi;
    {
        // w1 gate entries (G11 not needed)
        const float4* m4 = reinterpret_cast<const float4*>(mbase2 + 4);
        float4 ah = m4[0], bh = m4[1];
        float c = cs[1], s = sn[1];
        float2 g00 = make_float2(fmaf(c, ah.x, s * ah.z), fmaf(c, ah.y, s * ah.w));
        float2 g01 = make_float2(fmaf(-s, ah.x, c * ah.z), fmaf(-s, ah.y, c * ah.w));
        float2 g10 = make_float2(fmaf(c, bh.x, s * bh.z), fmaf(c, bh.y, s * bh.w));
        float alpha = fmaf(g00.x, g00.x, g00.y * g00.y)
                    - fmaf(g10.x, g10.x, g10.y * g10.y);
        float betr = 4.0f * fmaf(g00.x, g01.x, g00.y * g01.y);   // 4*Re(G00 conjG01)
        float beti = 4.0f * fmaf(g00.x, g01.y, -g00.y * g01.x);  // -4*Im(G00 conjG01)
        tA = sp2(alpha); tBr = sp2(betr); tBi = sp2(beti);
    }
    ull DP[8];
#pragma unroll
    for (int K = 0; K < 8; K++) {
        ull ar = RE[K], ai = IM[K], br = RE[K + 8], bi = IM[K + 8];
        ull na = fma2(ar, ar, mul2(ai, ai));                    // |a|^2
        ull nb = fma2(br, br, mul2(bi, bi));                    // |b|^2
        ull Z  = sub2f(na, nb, MONE);
        ull Rc = fma2(ai, bi, mul2(ar, br));                    // Re(a conj b)
        ull Ic = sub2f(mul2(ai, br), mul2(ar, bi), MONE);       // Im(a conj b)
        DP[K] = fma2(tA, Z, fma2(tBr, Rc, mul2(tBi, Ic)));
    }
    // Walsh butterfly on DP: bit0 first, then bit1, then bit2.
    ull A0 = add2(DP[0], DP[1]), A1 = add2(DP[2], DP[3]);
    ull A2 = add2(DP[4], DP[5]), A3 = add2(DP[6], DP[7]);
    ull D0 = sub2f(DP[0], DP[1], MONE), D1 = sub2f(DP[2], DP[3], MONE);
    ull D2 = sub2f(DP[4], DP[5], MONE), D3 = sub2f(DP[6], DP[7], MONE);
    ull S0 = add2(A0, A1), S1 = add2(A2, A3);
    ull U0 = sub2f(A0, A1, MONE), U1 = sub2f(A2, A3, MONE);
    ull V0 = sub2f(D0, D1, MONE), V1 = sub2f(D2, D3, MONE);
    ull E1v = add2(S0, S1);            // sign: wire1 only (in DP)
    ull E2v = sub2f(S0, S1, MONE);     // + wire2
    ull E3v = sub2f(U0, U1, MONE);     // + wires2,3
    ull E4v = sub2f(V0, V1, MONE);     // + wires2,3,4

    float sg = p ? -1.0f : 1.0f;
    float e1 = sg * (flo(E1v) + fhi(E1v));
    float e2 = sg * (flo(E2v) + fhi(E2v));
    float e3 = sg * (flo(E3v) + fhi(E3v));
    float e4 = sg * (flo(E4v) + fhi(E4v));
    float g5 = flo(E4v) - fhi(E4v);
    float e5 = sg * g5;
    float e0 = g5;

    e0 += __shfl_xor_sync(0xffffffffu, e0, 1);
    e1 += __shfl_xor_sync(0xffffffffu, e1, 1);
    e2 += __shfl_xor_sync(0xffffffffu, e2, 1);
    e3 += __shfl_xor_sync(0xffffffffu, e3, 1);
    e4 += __shfl_xor_sync(0xffffffffu, e4, 1);
    e5 += __shfl_xor_sync(0xffffffffu, e5, 1);

    float* ob = out + (size_t)b * NQ;
    if (p == 0) {
        *reinterpret_cast<float2*>(ob) = make_float2(e0, e1);
        ob[2] = e2;
    } else {
        ob[3] = e3;
        *reinterpret_cast<float2*>(ob + 4) = make_float2(e4, e5);
    }
}

extern "C" void kernel_launch(void* const* d_in, const int* in_sizes, int n_in,
                              void* d_out, int out_size) {
    const float* x = (const float*)d_in[0];
    const float* w = (const float*)d_in[1];
    float* out = (float*)d_out;
    int B = in_sizes[0] / NQ;

    const int threads = 128;
    long long total = 2LL * B;
    int blocks = (int)((total + threads - 1) / threads);
    qsim_kernel<<<blocks, threads>>>(x, w, out, B);
}